// round 11
// baseline (speedup 1.0000x reference)
#include <cuda_runtime.h>
#include <math.h>
#include <stdint.h>

#define Bsz 2
#define Ssz 1024
#define Dm  768
#define Hn  12
#define HDm 64
#define Ln  12
#define Vv  50304
#define TD  (Bsz*Ssz)   /* 2048 rows */
#define BK  32

typedef unsigned long long u64t;

// ================= helpers =================
__device__ __forceinline__ uint32_t smem_u32(const void* p) {
    uint32_t a;
    asm("{ .reg .u64 t; cvta.to.shared.u64 t, %1; cvt.u32.u64 %0, t; }" : "=r"(a) : "l"(p));
    return a;
}
#define CP_ASYNC16(s, g) asm volatile("cp.async.cg.shared.global [%0], [%1], 16;" :: "r"(s), "l"(g))
#define CP_COMMIT()      asm volatile("cp.async.commit_group;" ::: "memory")
#define CP_WAIT(n)       asm volatile("cp.async.wait_group %0;" :: "n"(n) : "memory")

__device__ __forceinline__ void ffma2(u64t& acc, u64t a, u64t b) {
    asm volatile("fma.rn.f32x2 %0, %1, %2, %0;" : "+l"(acc) : "l"(a), "l"(b));
}
__device__ __forceinline__ u64t splat2(float a) {
    u64t r; asm("mov.b64 %0, {%1, %1};" : "=l"(r) : "f"(a)); return r;
}
__device__ __forceinline__ u64t pack2(float lo, float hi) {
    u64t r; asm("mov.b64 %0, {%1, %2};" : "=l"(r) : "f"(lo), "f"(hi)); return r;
}
__device__ __forceinline__ float2 unpack2(u64t v) {
    float2 f; asm("mov.b64 {%0, %1}, %2;" : "=f"(f.x), "=f"(f.y) : "l"(v)); return f;
}

// ================= scratch =================
__device__ __align__(256) float g_x   [TD * Dm];
__device__ __align__(256) float g_h   [TD * Dm];
__device__ __align__(256) float g_qkv [TD * 3 * Dm];
__device__ __align__(256) float g_o   [TD * Dm];
__device__ __align__(256) float g_mlp [TD * 4 * Dm];
__device__ __align__(256) float g_madd[TD];
__device__ __align__(256) float g_wteT[(size_t)Dm * Vv];                // [768][50304]
__device__ __align__(256) float g_s   [(size_t)Bsz * Hn * Ssz * Ssz];  // scores/probs
__device__ __align__(256) float g_part [4][TD * Dm];                   // pv k-split partials
__device__ __align__(256) float g_gpart[3][TD * Dm];                   // proj/fc2 split-K partials
__device__ __align__(256) float g_fpart[2][TD * 4 * Dm];               // fc1 split-K partials

// ================= wte transpose =================
__global__ void transpose_wte(const float* __restrict__ w, float* __restrict__ wt) {
    __shared__ float t[32][33];
    int v0 = blockIdx.x * 32, d0 = blockIdx.y * 32;
#pragma unroll
    for (int i = 0; i < 4; i++)
        t[threadIdx.y + i * 8][threadIdx.x] =
            w[(size_t)(v0 + threadIdx.y + i * 8) * Dm + d0 + threadIdx.x];
    __syncthreads();
#pragma unroll
    for (int i = 0; i < 4; i++)
        wt[(size_t)(d0 + threadIdx.y + i * 8) * Vv + v0 + threadIdx.x] =
            t[threadIdx.x][threadIdx.y + i * 8];
}

// ================= embedding / mask =================
__global__ void embed_kernel(const int* __restrict__ ids, const float* __restrict__ wte,
                             const float* __restrict__ wpe, float* __restrict__ x) {
    int i = blockIdx.x * blockDim.x + threadIdx.x;
    if (i >= TD * Dm) return;
    int d = i % Dm, t = i / Dm, s = t % Ssz;
    x[i] = wte[(size_t)ids[t] * Dm + d] + wpe[(size_t)s * Dm + d];
}
__global__ void maskprep_kernel(const float* __restrict__ amask, float* __restrict__ madd) {
    int i = blockIdx.x * blockDim.x + threadIdx.x;
    if (i < TD) madd[i] = (1.0f - amask[i]) * -10000.0f;
}

// ================= layernorm (standalone: first ln1 only) =================
__global__ void ln_kernel(const float* __restrict__ x, const float* __restrict__ g,
                          const float* __restrict__ b, float* __restrict__ y, float eps) {
    int row = blockIdx.x, tid = threadIdx.x;
    const float* xr = x + (size_t)row * Dm;
    float v0 = xr[tid], v1 = xr[tid + 256], v2 = xr[tid + 512];
    __shared__ float red[256];
    red[tid] = v0 + v1 + v2;
    __syncthreads();
    for (int o = 128; o > 0; o >>= 1) { if (tid < o) red[tid] += red[tid + o]; __syncthreads(); }
    float mu = red[0] * (1.0f / Dm);
    __syncthreads();
    float d0 = v0 - mu, d1 = v1 - mu, d2 = v2 - mu;
    red[tid] = d0 * d0 + d1 * d1 + d2 * d2;
    __syncthreads();
    for (int o = 128; o > 0; o >>= 1) { if (tid < o) red[tid] += red[tid + o]; __syncthreads(); }
    float rstd = rsqrtf(red[0] * (1.0f / Dm) + eps);
    float* yr = y + (size_t)row * Dm;
    yr[tid]       = d0 * rstd * g[tid]       + b[tid];
    yr[tid + 256] = d1 * rstd * g[tid + 256] + b[tid + 256];
    yr[tid + 512] = d2 * rstd * g[tid + 512] + b[tid + 512];
}

// ========= fused: x = p0+p1+p2 + bias + res ;  h = LN(x; g,b,eps) =========
__global__ void redln_kernel(const float* __restrict__ Part, const float* __restrict__ bias,
                             const float* __restrict__ res, float* __restrict__ x,
                             const float* __restrict__ g, const float* __restrict__ b,
                             float* __restrict__ h, float eps) {
    int row = blockIdx.x, tid = threadIdx.x;
    size_t base = (size_t)row * Dm;
    float v[3];
#pragma unroll
    for (int j = 0; j < 3; j++) {
        int c = tid + j * 256;
        size_t idx = base + c;
        float s = ((Part[idx] + Part[(size_t)TD * Dm + idx]) + Part[2 * (size_t)TD * Dm + idx])
                  + bias[c] + res[idx];
        x[idx] = s;
        v[j] = s;
    }
    __shared__ float red[256];
    red[tid] = v[0] + v[1] + v[2];
    __syncthreads();
    for (int o = 128; o > 0; o >>= 1) { if (tid < o) red[tid] += red[tid + o]; __syncthreads(); }
    float mu = red[0] * (1.0f / Dm);
    __syncthreads();
    float d0 = v[0] - mu, d1 = v[1] - mu, d2 = v[2] - mu;
    red[tid] = d0 * d0 + d1 * d1 + d2 * d2;
    __syncthreads();
    for (int o = 128; o > 0; o >>= 1) { if (tid < o) red[tid] += red[tid + o]; __syncthreads(); }
    float rstd = rsqrtf(red[0] * (1.0f / Dm) + eps);
    float* hr = h + base;
    hr[tid]       = d0 * rstd * g[tid]       + b[tid];
    hr[tid + 256] = d1 * rstd * g[tid + 256] + b[tid + 256];
    hr[tid + 512] = d2 * rstd * g[tid + 512] + b[tid + 512];
}

// ========= fc1 reduce: mlp = gelu(p0 + p1 + bias) =========
__global__ void fc1reduce_kernel(const float* __restrict__ Part, const float* __restrict__ bias,
                                 float* __restrict__ mlp) {
    int i = blockIdx.x * blockDim.x + threadIdx.x;
    if (i >= TD * 4 * Dm) return;
    int n = i % (4 * Dm);
    float v = Part[i] + Part[(size_t)TD * 4 * Dm + i] + bias[n];
    mlp[i] = 0.5f * v * (1.0f + erff(v * 0.70710678118654752f));
}

// ================= attention: score GEMM S = Q K^T/8 (+mask) =================
#define SPAD 68
#define SCORE_SMEM (2 * 128 * SPAD * 4)
__global__ void __launch_bounds__(256)
score_kernel(const float* __restrict__ qkv, const float* __restrict__ madd,
             float* __restrict__ S) {
    int bh = blockIdx.z, b = bh / Hn, h = bh % Hn;
    int q0 = blockIdx.x * 128, k0 = blockIdx.y * 128;
    int tid = threadIdx.x, tx = tid & 15, ty = tid >> 4;

    if (blockIdx.y > blockIdx.x) {   // fully causal-masked tile
        float ma[8];
#pragma unroll
        for (int j = 0; j < 8; j++) ma[j] = -10000.0f + madd[b * Ssz + k0 + tx + 16 * j];
#pragma unroll
        for (int i = 0; i < 8; i++) {
            float* srow = S + ((size_t)bh * Ssz + q0 + ty * 8 + i) * Ssz + k0;
#pragma unroll
            for (int j = 0; j < 8; j++) srow[tx + 16 * j] = ma[j];
        }
        return;
    }

    extern __shared__ float sc_sm[];
    float* Qs = sc_sm;
    float* Ks = sc_sm + 128 * SPAD;
#pragma unroll
    for (int it = 0; it < 8; it++) {
        int idx = it * 256 + tid;
        int r = idx >> 4, c4 = idx & 15;
        float4 vq = *(const float4*)(qkv + (size_t)(b * Ssz + q0 + r) * (3 * Dm) + h * 3 * HDm + c4 * 4);
        *(float4*)(Qs + r * SPAD + c4 * 4) = vq;
        float4 vk = *(const float4*)(qkv + (size_t)(b * Ssz + k0 + r) * (3 * Dm) + h * 3 * HDm + HDm + c4 * 4);
        *(float4*)(Ks + r * SPAD + c4 * 4) = vk;
    }
    __syncthreads();

    u64t acc[8][4];
#pragma unroll
    for (int i = 0; i < 8; i++)
#pragma unroll
        for (int p = 0; p < 4; p++) acc[i][p] = 0ULL;

#pragma unroll 4
    for (int d = 0; d < HDm; d++) {
        float bv[8];
#pragma unroll
        for (int j = 0; j < 8; j++) bv[j] = Ks[(tx + 16 * j) * SPAD + d];
        u64t bp[4];
#pragma unroll
        for (int p = 0; p < 4; p++) bp[p] = pack2(bv[2 * p], bv[2 * p + 1]);
#pragma unroll
        for (int i = 0; i < 8; i++) {
            u64t aa = splat2(Qs[(ty * 8 + i) * SPAD + d]);
#pragma unroll
            for (int p = 0; p < 4; p++) ffma2(acc[i][p], aa, bp[p]);
        }
    }

    float ma[8];
#pragma unroll
    for (int j = 0; j < 8; j++) ma[j] = madd[b * Ssz + k0 + tx + 16 * j];
#pragma unroll
    for (int i = 0; i < 8; i++) {
        int q = q0 + ty * 8 + i;
        float* srow = S + ((size_t)bh * Ssz + q) * Ssz + k0;
#pragma unroll
        for (int p = 0; p < 4; p++) {
            float2 v = unpack2(acc[i][p]);
            int j0 = 2 * p, j1 = 2 * p + 1;
            int kg0 = k0 + tx + 16 * j0, kg1 = k0 + tx + 16 * j1;
            srow[tx + 16 * j0] = (kg0 <= q) ? v.x * 0.125f + ma[j0] : -10000.0f + ma[j0];
            srow[tx + 16 * j1] = (kg1 <= q) ? v.y * 0.125f + ma[j1] : -10000.0f + ma[j1];
        }
    }
}

// ================= attention: row softmax in place =================
__global__ void __launch_bounds__(256)
softmax_kernel(float* __restrict__ S) {
    size_t row = blockIdx.x;
    float* r = S + row * Ssz;
    int tid = threadIdx.x;
    float4 v = *(float4*)(r + tid * 4);
    __shared__ float red[256];
    red[tid] = fmaxf(fmaxf(v.x, v.y), fmaxf(v.z, v.w));
    __syncthreads();
    for (int o = 128; o > 0; o >>= 1) { if (tid < o) red[tid] = fmaxf(red[tid], red[tid + o]); __syncthreads(); }
    float mx = red[0];
    __syncthreads();
    v.x = __expf(v.x - mx); v.y = __expf(v.y - mx);
    v.z = __expf(v.z - mx); v.w = __expf(v.w - mx);
    red[tid] = v.x + v.y + v.z + v.w;
    __syncthreads();
    for (int o = 128; o > 0; o >>= 1) { if (tid < o) red[tid] += red[tid + o]; __syncthreads(); }
    float inv = 1.0f / red[0];
    v.x *= inv; v.y *= inv; v.z *= inv; v.w *= inv;
    *(float4*)(r + tid * 4) = v;
}

// ================= attention: O_partial = P slab @ V slab =================
#define PPAD 36
#define PS_FLOATS (128 * PPAD)
#define VS_FLOATS (32 * 64)
#define PV_SMEM (2 * (PS_FLOATS + VS_FLOATS) * 4)
__global__ void __launch_bounds__(256)
pv_kernel(const float* __restrict__ P, const float* __restrict__ qkv,
          float* __restrict__ part) {
    int bh = blockIdx.y, b = bh / Hn, h = bh % Hn;
    int q0 = blockIdx.x * 128;
    int ks = blockIdx.z;
    int kbase = ks * 256;
    if (kbase > q0 + 127) return;
    int tid = threadIdx.x, tx = tid & 7, ty = tid >> 3;

    extern __shared__ float pv_sm[];
    float* ps = pv_sm;
    float* vs = pv_sm + 2 * PS_FLOATS;
    const uint32_t sbP = smem_u32(pv_sm);
    const uint32_t sbV = sbP + 2 * PS_FLOATS * 4;

    const float* Pg = P + (size_t)bh * Ssz * Ssz;

    auto issueP = [&](int kc, int buf) {
        uint32_t base = sbP + buf * PS_FLOATS * 4;
#pragma unroll
        for (int it = 0; it < 4; it++) {
            int idx = it * 256 + tid;
            int r = idx >> 3, c4 = idx & 7;
            CP_ASYNC16(base + (uint32_t)(r * PPAD + c4 * 4) * 4,
                       Pg + (size_t)(q0 + r) * Ssz + kbase + kc * 32 + c4 * 4);
        }
    };
    auto issueV = [&](int kc, int buf) {
        uint32_t base = sbV + buf * VS_FLOATS * 4;
#pragma unroll
        for (int it = 0; it < 2; it++) {
            int idx = it * 256 + tid;
            int r = idx >> 4, c4 = idx & 15;
            CP_ASYNC16(base + (uint32_t)(r * 64 + c4 * 4) * 4,
                       qkv + (size_t)(b * Ssz + kbase + kc * 32 + r) * (3 * Dm) + h * 3 * HDm + 2 * HDm + c4 * 4);
        }
    };

    u64t acc[4][4];
#pragma unroll
    for (int i = 0; i < 4; i++)
#pragma unroll
        for (int j = 0; j < 4; j++) acc[i][j] = 0ULL;

    const int NCK = 8;
    issueP(0, 0); issueV(0, 0); CP_COMMIT();
    for (int cc = 0; cc < NCK; cc++) {
        if (cc + 1 < NCK) {
            issueP(cc + 1, (cc + 1) & 1); issueV(cc + 1, (cc + 1) & 1); CP_COMMIT();
            CP_WAIT(1);
        } else {
            CP_WAIT(0);
        }
        __syncthreads();
        const float* Pb = ps + (cc & 1) * PS_FLOATS;
        const float* Vb = vs + (cc & 1) * VS_FLOATS;
#pragma unroll 4
        for (int k = 0; k < 32; k++) {
            const float* vrow = Vb + k * 64 + tx * 8;
            u64t b0 = *(const u64t*)(vrow);
            u64t b1 = *(const u64t*)(vrow + 2);
            u64t b2 = *(const u64t*)(vrow + 4);
            u64t b3 = *(const u64t*)(vrow + 6);
#pragma unroll
            for (int i = 0; i < 4; i++) {
                u64t aa = splat2(Pb[(ty * 4 + i) * PPAD + k]);
                ffma2(acc[i][0], aa, b0);
                ffma2(acc[i][1], aa, b1);
                ffma2(acc[i][2], aa, b2);
                ffma2(acc[i][3], aa, b3);
            }
        }
        __syncthreads();
    }

    float* op = part + (size_t)ks * TD * Dm;
#pragma unroll
    for (int i = 0; i < 4; i++) {
        int q = q0 + ty * 4 + i;
        float* orow = op + (size_t)(b * Ssz + q) * Dm + h * HDm + tx * 8;
        float2 p0 = unpack2(acc[i][0]), p1 = unpack2(acc[i][1]);
        float2 p2 = unpack2(acc[i][2]), p3 = unpack2(acc[i][3]);
        *(float4*)(orow)     = make_float4(p0.x, p0.y, p1.x, p1.y);
        *(float4*)(orow + 4) = make_float4(p2.x, p2.y, p3.x, p3.y);
    }
}

// ================= pv partial reduce =================
__global__ void pvreduce_kernel(const float* __restrict__ part, float* __restrict__ O) {
    int i = blockIdx.x * blockDim.x + threadIdx.x;
    if (i >= TD * Dm) return;
    int t = i / Dm;
    int q = t % Ssz;
    int q0 = q & ~127;
    int ns = (q0 + 127) / 256 + 1;
    float s = part[i];
    if (ns > 1) s += part[(size_t)TD * Dm + i];
    if (ns > 2) s += part[2 * (size_t)TD * Dm + i];
    if (ns > 3) s += part[3 * (size_t)TD * Dm + i];
    O[i] = s;
}

// ================= fp32 FFMA2 GEMM (NN), BK=32, CTA 128x128 =================
// epi 0: bias | 1: bias+gelu(exact)
#define GEMM_SMEM_128 (3 * (128 * 36 + 32 * 128) * 4)
__global__ void __launch_bounds__(256, 2)
gemm_f32(const float* __restrict__ A, const float* __restrict__ B,
         const float* __restrict__ bias, float* __restrict__ C,
         int M, int N, int K, int epi) {
    constexpr int ASZF = 128 * 36;
    constexpr int BSZF = 32 * 128;
    extern __shared__ float sm[];
    float* as_ = sm;
    float* bs_ = sm + 3 * ASZF;
    const uint32_t sbA = smem_u32(sm);
    const uint32_t sbB = sbA + 3 * ASZF * 4;
    const int tid = threadIdx.x;
    const int tx = tid & 15, ty = tid >> 4;
    const int m0 = blockIdx.x * 128;
    const int n0 = blockIdx.y * 128;

    u64t acc[8][4];
#pragma unroll
    for (int i = 0; i < 8; i++)
#pragma unroll
        for (int j = 0; j < 4; j++) acc[i][j] = 0ULL;

    const int NC = K / BK;
    const float* gA = A + (size_t)m0 * K;
    const float* gB = B + n0;

    auto issueA = [&](int kc, int buf) {
        uint32_t base = sbA + buf * ASZF * 4;
        int k0 = kc * BK;
#pragma unroll
        for (int p = 0; p < 4; p++) {
            int idx = p * 256 + tid;
            int r = idx >> 3, c4 = idx & 7;
            CP_ASYNC16(base + (uint32_t)(r * 36 + c4 * 4) * 4,
                       gA + (size_t)r * K + k0 + c4 * 4);
        }
    };
    auto issueB = [&](int kc, int buf) {
        uint32_t base = sbB + buf * BSZF * 4;
        int k0 = kc * BK;
#pragma unroll
        for (int p = 0; p < 4; p++) {
            int idx = p * 256 + tid;
            int r = idx >> 5, c4 = idx & 31;
            CP_ASYNC16(base + (uint32_t)(r * 128 + c4 * 4) * 4,
                       gB + (size_t)(k0 + r) * N + c4 * 4);
        }
    };

    auto compute = [&](int buf) {
        const float* Ab = as_ + buf * ASZF;
        const float* Bb = bs_ + buf * BSZF;
#pragma unroll 8
        for (int h = 0; h < 16; h++) {
            float2 a2[8];
#pragma unroll
            for (int i = 0; i < 8; i++)
                a2[i] = *(const float2*)(Ab + (ty * 8 + i) * 36 + h * 2);
#pragma unroll
            for (int k2 = 0; k2 < 2; k2++) {
                const float* brow = Bb + (h * 2 + k2) * 128 + tx * 8;
                u64t b0 = *(const u64t*)(brow);
                u64t b1 = *(const u64t*)(brow + 2);
                u64t b2 = *(const u64t*)(brow + 4);
                u64t b3 = *(const u64t*)(brow + 6);
#pragma unroll
                for (int i = 0; i < 8; i++) {
                    u64t aa = splat2(k2 ? a2[i].y : a2[i].x);
                    ffma2(acc[i][0], aa, b0);
                    ffma2(acc[i][1], aa, b1);
                    ffma2(acc[i][2], aa, b2);
                    ffma2(acc[i][3], aa, b3);
                }
            }
        }
    };

    issueA(0, 0); issueB(0, 0); CP_COMMIT();
    issueA(1, 1); issueB(1, 1); CP_COMMIT();
    for (int cc = 0; cc < NC; cc++) {
        if (cc + 1 < NC) { CP_WAIT(1); } else { CP_WAIT(0); }
        __syncthreads();
        if (cc + 2 < NC) {
            int nb = (cc + 2) % 3;
            issueA(cc + 2, nb); issueB(cc + 2, nb); CP_COMMIT();
        }
        compute(cc % 3);
    }

    const int ncol = n0 + tx * 8;
    float4 bb0 = *(const float4*)(bias + ncol);
    float4 bb1 = *(const float4*)(bias + ncol + 4);
#pragma unroll
    for (int i = 0; i < 8; i++) {
        int m = m0 + ty * 8 + i;
        size_t off = (size_t)m * N + ncol;
        float o[8];
        float2 p;
        p = unpack2(acc[i][0]); o[0] = p.x + bb0.x; o[1] = p.y + bb0.y;
        p = unpack2(acc[i][1]); o[2] = p.x + bb0.z; o[3] = p.y + bb0.w;
        p = unpack2(acc[i][2]); o[4] = p.x + bb1.x; o[5] = p.y + bb1.y;
        p = unpack2(acc[i][3]); o[6] = p.x + bb1.z; o[7] = p.y + bb1.w;
        if (epi == 1) {
#pragma unroll
            for (int j = 0; j < 8; j++) {
                float g = o[j];
                o[j] = 0.5f * g * (1.0f + erff(g * 0.70710678118654752f));
            }
        }
        *(float4*)(C + off)     = make_float4(o[0], o[1], o[2], o[3]);
        *(float4*)(C + off + 4) = make_float4(o[4], o[5], o[6], o[7]);
    }
}

// ================= split-K GEMM partial: raw slab output =================
// grid (Mtiles, Ntiles, KSplits); slab ks covers K rows [ks*KS, (ks+1)*KS)
// Part slab stride = M*N (passed as slabStride)
__global__ void __launch_bounds__(256, 2)
gemm_pk(const float* __restrict__ A, const float* __restrict__ B,
        float* __restrict__ Part, int M, int N, int K, int KS, size_t slabStride) {
    constexpr int ASZF = 128 * 36;
    constexpr int BSZF = 32 * 128;
    extern __shared__ float sm[];
    float* as_ = sm;
    float* bs_ = sm + 3 * ASZF;
    const uint32_t sbA = smem_u32(sm);
    const uint32_t sbB = sbA + 3 * ASZF * 4;
    const int tid = threadIdx.x;
    const int tx = tid & 15, ty = tid >> 4;
    const int m0 = blockIdx.x * 128;
    const int n0 = blockIdx.y * 128;
    const int ks = blockIdx.z;
    const int kbeg = ks * KS;

    u64t acc[8][4];
#pragma unroll
    for (int i = 0; i < 8; i++)
#pragma unroll
        for (int j = 0; j < 4; j++) acc[i][j] = 0ULL;

    const int NC = KS / BK;
    const float* gA = A + (size_t)m0 * K + kbeg;
    const float* gB = B + (size_t)kbeg * N + n0;

    auto issueA = [&](int kc, int buf) {
        uint32_t base = sbA + buf * ASZF * 4;
        int k0 = kc * BK;
#pragma unroll
        for (int p = 0; p < 4; p++) {
            int idx = p * 256 + tid;
            int r = idx >> 3, c4 = idx & 7;
            CP_ASYNC16(base + (uint32_t)(r * 36 + c4 * 4) * 4,
                       gA + (size_t)r * K + k0 + c4 * 4);
        }
    };
    auto issueB = [&](int kc, int buf) {
        uint32_t base = sbB + buf * BSZF * 4;
        int k0 = kc * BK;
#pragma unroll
        for (int p = 0; p < 4; p++) {
            int idx = p * 256 + tid;
            int r = idx >> 5, c4 = idx & 31;
            CP_ASYNC16(base + (uint32_t)(r * 128 + c4 * 4) * 4,
                       gB + (size_t)(k0 + r) * N + c4 * 4);
        }
    };

    auto compute = [&](int buf) {
        const float* Ab = as_ + buf * ASZF;
        const float* Bb = bs_ + buf * BSZF;
#pragma unroll 8
        for (int h = 0; h < 16; h++) {
            float2 a2[8];
#pragma unroll
            for (int i = 0; i < 8; i++)
                a2[i] = *(const float2*)(Ab + (ty * 8 + i) * 36 + h * 2);
#pragma unroll
            for (int k2 = 0; k2 < 2; k2++) {
                const float* brow = Bb + (h * 2 + k2) * 128 + tx * 8;
                u64t b0 = *(const u64t*)(brow);
                u64t b1 = *(const u64t*)(brow + 2);
                u64t b2 = *(const u64t*)(brow + 4);
                u64t b3 = *(const u64t*)(brow + 6);
#pragma unroll
                for (int i = 0; i < 8; i++) {
                    u64t aa = splat2(k2 ? a2[i].y : a2[i].x);
                    ffma2(acc[i][0], aa, b0);
                    ffma2(acc[i][1], aa, b1);
                    ffma2(acc[i][2], aa, b2);
                    ffma2(acc[i][3], aa, b3);
                }
            }
        }
    };

    issueA(0, 0); issueB(0, 0); CP_COMMIT();
    issueA(1, 1); issueB(1, 1); CP_COMMIT();
    for (int cc = 0; cc < NC; cc++) {
        if (cc + 1 < NC) { CP_WAIT(1); } else { CP_WAIT(0); }
        __syncthreads();
        if (cc + 2 < NC) {
            int nb = (cc + 2) % 3;
            issueA(cc + 2, nb); issueB(cc + 2, nb); CP_COMMIT();
        }
        compute(cc % 3);
    }

    float* P = Part + (size_t)ks * slabStride;
    const int ncol = n0 + tx * 8;
#pragma unroll
    for (int i = 0; i < 8; i++) {
        int m = m0 + ty * 8 + i;
        size_t off = (size_t)m * N + ncol;
        float2 p0 = unpack2(acc[i][0]), p1 = unpack2(acc[i][1]);
        float2 p2 = unpack2(acc[i][2]), p3 = unpack2(acc[i][3]);
        *(float4*)(P + off)     = make_float4(p0.x, p0.y, p1.x, p1.y);
        *(float4*)(P + off + 4) = make_float4(p2.x, p2.y, p3.x, p3.y);
    }
}

// ================= host orchestration =================
extern "C" void kernel_launch(void* const* d_in, const int* in_sizes, int n_in,
                              void* d_out, int out_size) {
    const int*   ids    = (const int*)  d_in[0];
    const float* amask  = (const float*)d_in[1];
    const float* wte    = (const float*)d_in[2];
    const float* wpe    = (const float*)d_in[3];
    const float* ln1_g  = (const float*)d_in[4];
    const float* ln1_b  = (const float*)d_in[5];
    const float* qkv_w  = (const float*)d_in[6];
    const float* qkv_b  = (const float*)d_in[7];
    const float* proj_w = (const float*)d_in[8];
    const float* proj_b = (const float*)d_in[9];
    const float* ln2_g  = (const float*)d_in[10];
    const float* ln2_b  = (const float*)d_in[11];
    const float* fc1_w  = (const float*)d_in[12];
    const float* fc1_b  = (const float*)d_in[13];
    const float* fc2_w  = (const float*)d_in[14];
    const float* fc2_b  = (const float*)d_in[15];
    const float* lnf_g  = (const float*)d_in[16];
    const float* lnf_b  = (const float*)d_in[17];
    const float* head_b = (const float*)d_in[18];
    float* out = (float*)d_out;

    float *x, *h, *qkv, *o, *mlp, *madd, *wteT, *S, *part, *gpart, *fpart;
    cudaGetSymbolAddress((void**)&x,     g_x);
    cudaGetSymbolAddress((void**)&h,     g_h);
    cudaGetSymbolAddress((void**)&qkv,   g_qkv);
    cudaGetSymbolAddress((void**)&o,     g_o);
    cudaGetSymbolAddress((void**)&mlp,   g_mlp);
    cudaGetSymbolAddress((void**)&madd,  g_madd);
    cudaGetSymbolAddress((void**)&wteT,  g_wteT);
    cudaGetSymbolAddress((void**)&S,     g_s);
    cudaGetSymbolAddress((void**)&part,  g_part);
    cudaGetSymbolAddress((void**)&gpart, g_gpart);
    cudaGetSymbolAddress((void**)&fpart, g_fpart);

    cudaFuncSetAttribute(gemm_f32,     cudaFuncAttributeMaxDynamicSharedMemorySize, GEMM_SMEM_128);
    cudaFuncSetAttribute(gemm_pk,      cudaFuncAttributeMaxDynamicSharedMemorySize, GEMM_SMEM_128);
    cudaFuncSetAttribute(score_kernel, cudaFuncAttributeMaxDynamicSharedMemorySize, SCORE_SMEM);
    cudaFuncSetAttribute(pv_kernel,    cudaFuncAttributeMaxDynamicSharedMemorySize, PV_SMEM);

    // launch order: embed(0), mask(1), ln(2), QKV gemm(3) <- ncu capture slot
    embed_kernel<<<(TD * Dm + 255) / 256, 256>>>(ids, wte, wpe, x);
    maskprep_kernel<<<(TD + 255) / 256, 256>>>(amask, madd);
    ln_kernel<<<TD, 256>>>(x, ln1_g, ln1_b, h, 1e-6f);   // ln1 of layer 0

    for (int l = 0; l < Ln; l++) {
        // QKV: [2048,768] @ [768,2304]  grid 16x18 = 288
        gemm_f32<<<dim3(TD / 128, 3 * Dm / 128), 256, GEMM_SMEM_128>>>(
            h, qkv_w + (size_t)l * Dm * 3 * Dm, qkv_b + (size_t)l * 3 * Dm,
            qkv, TD, 3 * Dm, Dm, 0);
        // attention
        score_kernel<<<dim3(Ssz / 128, Ssz / 128, Bsz * Hn), 256, SCORE_SMEM>>>(qkv, madd, S);
        softmax_kernel<<<Bsz * Hn * Ssz, 256>>>(S);
        pv_kernel<<<dim3(Ssz / 128, Bsz * Hn, 4), 256, PV_SMEM>>>(S, qkv, part);
        pvreduce_kernel<<<(TD * Dm + 255) / 256, 256>>>(part, o);
        // proj: split-K=3, grid 16x6x3 = 288 CTAs; fused reduce+residual+LN2 -> x, h
        gemm_pk<<<dim3(TD / 128, Dm / 128, 3), 256, GEMM_SMEM_128>>>(
            o, proj_w + (size_t)l * Dm * Dm, gpart, TD, Dm, Dm, Dm / 3, (size_t)TD * Dm);
        redln_kernel<<<TD, 256>>>(gpart, proj_b + (size_t)l * Dm, x, x,
                                  ln2_g + l * Dm, ln2_b + l * Dm, h, 1e-6f);
        // fc1: split-K=2, grid 16x24x2 = 768 CTAs; reduce+gelu -> mlp
        gemm_pk<<<dim3(TD / 128, 4 * Dm / 128, 2), 256, GEMM_SMEM_128>>>(
            h, fc1_w + (size_t)l * Dm * 4 * Dm, fpart, TD, 4 * Dm, Dm, Dm / 2,
            (size_t)TD * 4 * Dm);
        fc1reduce_kernel<<<(TD * 4 * Dm + 255) / 256, 256>>>(fpart, fc1_b + (size_t)l * 4 * Dm, mlp);
        // fc2: split-K=3, grid 16x6x3 = 288 CTAs; fused reduce+residual+LN(next) -> x, h
        gemm_pk<<<dim3(TD / 128, Dm / 128, 3), 256, GEMM_SMEM_128>>>(
            mlp, fc2_w + (size_t)l * 4 * Dm * Dm, gpart, TD, Dm, 4 * Dm, 4 * Dm / 3,
            (size_t)TD * Dm);
        if (l + 1 < Ln) {
            redln_kernel<<<TD, 256>>>(gpart, fc2_b + (size_t)l * Dm, x, x,
                                      ln1_g + (l + 1) * Dm, ln1_b + (l + 1) * Dm, h, 1e-6f);
        } else {
            redln_kernel<<<TD, 256>>>(gpart, fc2_b + (size_t)l * Dm, x, x,
                                      lnf_g, lnf_b, h, 1e-5f);   // final LN
        }
    }

    transpose_wte<<<dim3(Vv / 32, Dm / 32), dim3(32, 8)>>>(wte, wteT);

    // LM head: [2048,768] @ wteT[768,50304]  grid 16x393 = 6288
    gemm_f32<<<dim3(TD / 128, Vv / 128), 256, GEMM_SMEM_128>>>(
        h, wteT, head_b, out, TD, Vv, Dm, 0);
}

// round 12
// speedup vs baseline: 1.0164x; 1.0164x over previous
#include <cuda_runtime.h>
#include <math.h>
#include <stdint.h>

#define Bsz 2
#define Ssz 1024
#define Dm  768
#define Hn  12
#define HDm 64
#define Ln  12
#define Vv  50304
#define TD  (Bsz*Ssz)   /* 2048 rows */
#define BK  32

typedef unsigned long long u64t;

// ================= helpers =================
__device__ __forceinline__ uint32_t smem_u32(const void* p) {
    uint32_t a;
    asm("{ .reg .u64 t; cvta.to.shared.u64 t, %1; cvt.u32.u64 %0, t; }" : "=r"(a) : "l"(p));
    return a;
}
#define CP_ASYNC16(s, g) asm volatile("cp.async.cg.shared.global [%0], [%1], 16;" :: "r"(s), "l"(g))
#define CP_COMMIT()      asm volatile("cp.async.commit_group;" ::: "memory")
#define CP_WAIT(n)       asm volatile("cp.async.wait_group %0;" :: "n"(n) : "memory")

__device__ __forceinline__ void ffma2(u64t& acc, u64t a, u64t b) {
    asm volatile("fma.rn.f32x2 %0, %1, %2, %0;" : "+l"(acc) : "l"(a), "l"(b));
}
__device__ __forceinline__ u64t splat2(float a) {
    u64t r; asm("mov.b64 %0, {%1, %1};" : "=l"(r) : "f"(a)); return r;
}
__device__ __forceinline__ u64t pack2(float lo, float hi) {
    u64t r; asm("mov.b64 %0, {%1, %2};" : "=l"(r) : "f"(lo), "f"(hi)); return r;
}
__device__ __forceinline__ float2 unpack2(u64t v) {
    float2 f; asm("mov.b64 {%0, %1}, %2;" : "=f"(f.x), "=f"(f.y) : "l"(v)); return f;
}

// ================= scratch =================
__device__ __align__(256) float g_x   [TD * Dm];
__device__ __align__(256) float g_h   [TD * Dm];
__device__ __align__(256) float g_qkv [TD * 3 * Dm];
__device__ __align__(256) float g_o   [TD * Dm];
__device__ __align__(256) float g_mlp [TD * 4 * Dm];
__device__ __align__(256) float g_madd[TD];
__device__ __align__(256) float g_wteT[(size_t)Dm * Vv];                // [768][50304]
__device__ __align__(256) float g_s   [(size_t)Bsz * Hn * Ssz * Ssz];  // scores/probs
__device__ __align__(256) float g_part [4][TD * Dm];                   // pv k-split partials
__device__ __align__(256) float g_gpart[3][TD * Dm];                   // proj/fc2 split-K partials

// ================= wte transpose =================
__global__ void transpose_wte(const float* __restrict__ w, float* __restrict__ wt) {
    __shared__ float t[32][33];
    int v0 = blockIdx.x * 32, d0 = blockIdx.y * 32;
#pragma unroll
    for (int i = 0; i < 4; i++)
        t[threadIdx.y + i * 8][threadIdx.x] =
            w[(size_t)(v0 + threadIdx.y + i * 8) * Dm + d0 + threadIdx.x];
    __syncthreads();
#pragma unroll
    for (int i = 0; i < 4; i++)
        wt[(size_t)(d0 + threadIdx.y + i * 8) * Vv + v0 + threadIdx.x] =
            t[threadIdx.x][threadIdx.y + i * 8];
}

// ================= embedding / mask =================
__global__ void embed_kernel(const int* __restrict__ ids, const float* __restrict__ wte,
                             const float* __restrict__ wpe, float* __restrict__ x) {
    int i = blockIdx.x * blockDim.x + threadIdx.x;
    if (i >= TD * Dm) return;
    int d = i % Dm, t = i / Dm, s = t % Ssz;
    x[i] = wte[(size_t)ids[t] * Dm + d] + wpe[(size_t)s * Dm + d];
}
__global__ void maskprep_kernel(const float* __restrict__ amask, float* __restrict__ madd) {
    int i = blockIdx.x * blockDim.x + threadIdx.x;
    if (i < TD) madd[i] = (1.0f - amask[i]) * -10000.0f;
}

// ================= layernorm (standalone: first ln1 only) =================
__global__ void ln_kernel(const float* __restrict__ x, const float* __restrict__ g,
                          const float* __restrict__ b, float* __restrict__ y, float eps) {
    int row = blockIdx.x, tid = threadIdx.x;
    const float* xr = x + (size_t)row * Dm;
    float v0 = xr[tid], v1 = xr[tid + 256], v2 = xr[tid + 512];
    __shared__ float red[256];
    red[tid] = v0 + v1 + v2;
    __syncthreads();
    for (int o = 128; o > 0; o >>= 1) { if (tid < o) red[tid] += red[tid + o]; __syncthreads(); }
    float mu = red[0] * (1.0f / Dm);
    __syncthreads();
    float d0 = v0 - mu, d1 = v1 - mu, d2 = v2 - mu;
    red[tid] = d0 * d0 + d1 * d1 + d2 * d2;
    __syncthreads();
    for (int o = 128; o > 0; o >>= 1) { if (tid < o) red[tid] += red[tid + o]; __syncthreads(); }
    float rstd = rsqrtf(red[0] * (1.0f / Dm) + eps);
    float* yr = y + (size_t)row * Dm;
    yr[tid]       = d0 * rstd * g[tid]       + b[tid];
    yr[tid + 256] = d1 * rstd * g[tid + 256] + b[tid + 256];
    yr[tid + 512] = d2 * rstd * g[tid + 512] + b[tid + 512];
}

// ========= fused: x = p0+p1+p2 + bias + res ;  h = LN(x; g,b,eps) =========
__global__ void redln_kernel(const float* __restrict__ Part, const float* __restrict__ bias,
                             const float* __restrict__ res, float* __restrict__ x,
                             const float* __restrict__ g, const float* __restrict__ b,
                             float* __restrict__ h, float eps) {
    int row = blockIdx.x, tid = threadIdx.x;
    size_t base = (size_t)row * Dm;
    float v[3];
#pragma unroll
    for (int j = 0; j < 3; j++) {
        int c = tid + j * 256;
        size_t idx = base + c;
        float s = ((Part[idx] + Part[(size_t)TD * Dm + idx]) + Part[2 * (size_t)TD * Dm + idx])
                  + bias[c] + res[idx];
        x[idx] = s;
        v[j] = s;
    }
    __shared__ float red[256];
    red[tid] = v[0] + v[1] + v[2];
    __syncthreads();
    for (int o = 128; o > 0; o >>= 1) { if (tid < o) red[tid] += red[tid + o]; __syncthreads(); }
    float mu = red[0] * (1.0f / Dm);
    __syncthreads();
    float d0 = v[0] - mu, d1 = v[1] - mu, d2 = v[2] - mu;
    red[tid] = d0 * d0 + d1 * d1 + d2 * d2;
    __syncthreads();
    for (int o = 128; o > 0; o >>= 1) { if (tid < o) red[tid] += red[tid + o]; __syncthreads(); }
    float rstd = rsqrtf(red[0] * (1.0f / Dm) + eps);
    float* hr = h + base;
    hr[tid]       = d0 * rstd * g[tid]       + b[tid];
    hr[tid + 256] = d1 * rstd * g[tid + 256] + b[tid + 256];
    hr[tid + 512] = d2 * rstd * g[tid + 512] + b[tid + 512];
}

// ================= attention: score GEMM S = Q K^T/8 (+mask) =================
#define SPAD 68
#define SCORE_SMEM (2 * 128 * SPAD * 4)
__global__ void __launch_bounds__(256)
score_kernel(const float* __restrict__ qkv, const float* __restrict__ madd,
             float* __restrict__ S) {
    int bh = blockIdx.z, b = bh / Hn, h = bh % Hn;
    int q0 = blockIdx.x * 128, k0 = blockIdx.y * 128;
    int tid = threadIdx.x, tx = tid & 15, ty = tid >> 4;

    if (blockIdx.y > blockIdx.x) {   // fully causal-masked tile
        float ma[8];
#pragma unroll
        for (int j = 0; j < 8; j++) ma[j] = -10000.0f + madd[b * Ssz + k0 + tx + 16 * j];
#pragma unroll
        for (int i = 0; i < 8; i++) {
            float* srow = S + ((size_t)bh * Ssz + q0 + ty * 8 + i) * Ssz + k0;
#pragma unroll
            for (int j = 0; j < 8; j++) srow[tx + 16 * j] = ma[j];
        }
        return;
    }

    extern __shared__ float sc_sm[];
    float* Qs = sc_sm;
    float* Ks = sc_sm + 128 * SPAD;
#pragma unroll
    for (int it = 0; it < 8; it++) {
        int idx = it * 256 + tid;
        int r = idx >> 4, c4 = idx & 15;
        float4 vq = *(const float4*)(qkv + (size_t)(b * Ssz + q0 + r) * (3 * Dm) + h * 3 * HDm + c4 * 4);
        *(float4*)(Qs + r * SPAD + c4 * 4) = vq;
        float4 vk = *(const float4*)(qkv + (size_t)(b * Ssz + k0 + r) * (3 * Dm) + h * 3 * HDm + HDm + c4 * 4);
        *(float4*)(Ks + r * SPAD + c4 * 4) = vk;
    }
    __syncthreads();

    u64t acc[8][4];
#pragma unroll
    for (int i = 0; i < 8; i++)
#pragma unroll
        for (int p = 0; p < 4; p++) acc[i][p] = 0ULL;

#pragma unroll 4
    for (int d = 0; d < HDm; d++) {
        float bv[8];
#pragma unroll
        for (int j = 0; j < 8; j++) bv[j] = Ks[(tx + 16 * j) * SPAD + d];
        u64t bp[4];
#pragma unroll
        for (int p = 0; p < 4; p++) bp[p] = pack2(bv[2 * p], bv[2 * p + 1]);
#pragma unroll
        for (int i = 0; i < 8; i++) {
            u64t aa = splat2(Qs[(ty * 8 + i) * SPAD + d]);
#pragma unroll
            for (int p = 0; p < 4; p++) ffma2(acc[i][p], aa, bp[p]);
        }
    }

    float ma[8];
#pragma unroll
    for (int j = 0; j < 8; j++) ma[j] = madd[b * Ssz + k0 + tx + 16 * j];
#pragma unroll
    for (int i = 0; i < 8; i++) {
        int q = q0 + ty * 8 + i;
        float* srow = S + ((size_t)bh * Ssz + q) * Ssz + k0;
#pragma unroll
        for (int p = 0; p < 4; p++) {
            float2 v = unpack2(acc[i][p]);
            int j0 = 2 * p, j1 = 2 * p + 1;
            int kg0 = k0 + tx + 16 * j0, kg1 = k0 + tx + 16 * j1;
            srow[tx + 16 * j0] = (kg0 <= q) ? v.x * 0.125f + ma[j0] : -10000.0f + ma[j0];
            srow[tx + 16 * j1] = (kg1 <= q) ? v.y * 0.125f + ma[j1] : -10000.0f + ma[j1];
        }
    }
}

// ================= attention: row softmax in place =================
__global__ void __launch_bounds__(256)
softmax_kernel(float* __restrict__ S) {
    size_t row = blockIdx.x;
    float* r = S + row * Ssz;
    int tid = threadIdx.x;
    float4 v = *(float4*)(r + tid * 4);
    __shared__ float red[256];
    red[tid] = fmaxf(fmaxf(v.x, v.y), fmaxf(v.z, v.w));
    __syncthreads();
    for (int o = 128; o > 0; o >>= 1) { if (tid < o) red[tid] = fmaxf(red[tid], red[tid + o]); __syncthreads(); }
    float mx = red[0];
    __syncthreads();
    v.x = __expf(v.x - mx); v.y = __expf(v.y - mx);
    v.z = __expf(v.z - mx); v.w = __expf(v.w - mx);
    red[tid] = v.x + v.y + v.z + v.w;
    __syncthreads();
    for (int o = 128; o > 0; o >>= 1) { if (tid < o) red[tid] += red[tid + o]; __syncthreads(); }
    float inv = 1.0f / red[0];
    v.x *= inv; v.y *= inv; v.z *= inv; v.w *= inv;
    *(float4*)(r + tid * 4) = v;
}

// ================= attention: O_partial = P slab @ V slab =================
#define PPAD 36
#define PS_FLOATS (128 * PPAD)
#define VS_FLOATS (32 * 64)
#define PV_SMEM (2 * (PS_FLOATS + VS_FLOATS) * 4)
__global__ void __launch_bounds__(256)
pv_kernel(const float* __restrict__ P, const float* __restrict__ qkv,
          float* __restrict__ part) {
    int bh = blockIdx.y, b = bh / Hn, h = bh % Hn;
    int q0 = blockIdx.x * 128;
    int ks = blockIdx.z;
    int kbase = ks * 256;
    if (kbase > q0 + 127) return;
    int tid = threadIdx.x, tx = tid & 7, ty = tid >> 3;

    extern __shared__ float pv_sm[];
    float* ps = pv_sm;
    float* vs = pv_sm + 2 * PS_FLOATS;
    const uint32_t sbP = smem_u32(pv_sm);
    const uint32_t sbV = sbP + 2 * PS_FLOATS * 4;

    const float* Pg = P + (size_t)bh * Ssz * Ssz;

    auto issueP = [&](int kc, int buf) {
        uint32_t base = sbP + buf * PS_FLOATS * 4;
#pragma unroll
        for (int it = 0; it < 4; it++) {
            int idx = it * 256 + tid;
            int r = idx >> 3, c4 = idx & 7;
            CP_ASYNC16(base + (uint32_t)(r * PPAD + c4 * 4) * 4,
                       Pg + (size_t)(q0 + r) * Ssz + kbase + kc * 32 + c4 * 4);
        }
    };
    auto issueV = [&](int kc, int buf) {
        uint32_t base = sbV + buf * VS_FLOATS * 4;
#pragma unroll
        for (int it = 0; it < 2; it++) {
            int idx = it * 256 + tid;
            int r = idx >> 4, c4 = idx & 15;
            CP_ASYNC16(base + (uint32_t)(r * 64 + c4 * 4) * 4,
                       qkv + (size_t)(b * Ssz + kbase + kc * 32 + r) * (3 * Dm) + h * 3 * HDm + 2 * HDm + c4 * 4);
        }
    };

    u64t acc[4][4];
#pragma unroll
    for (int i = 0; i < 4; i++)
#pragma unroll
        for (int j = 0; j < 4; j++) acc[i][j] = 0ULL;

    const int NCK = 8;
    issueP(0, 0); issueV(0, 0); CP_COMMIT();
    for (int cc = 0; cc < NCK; cc++) {
        if (cc + 1 < NCK) {
            issueP(cc + 1, (cc + 1) & 1); issueV(cc + 1, (cc + 1) & 1); CP_COMMIT();
            CP_WAIT(1);
        } else {
            CP_WAIT(0);
        }
        __syncthreads();
        const float* Pb = ps + (cc & 1) * PS_FLOATS;
        const float* Vb = vs + (cc & 1) * VS_FLOATS;
#pragma unroll 4
        for (int k = 0; k < 32; k++) {
            const float* vrow = Vb + k * 64 + tx * 8;
            u64t b0 = *(const u64t*)(vrow);
            u64t b1 = *(const u64t*)(vrow + 2);
            u64t b2 = *(const u64t*)(vrow + 4);
            u64t b3 = *(const u64t*)(vrow + 6);
#pragma unroll
            for (int i = 0; i < 4; i++) {
                u64t aa = splat2(Pb[(ty * 4 + i) * PPAD + k]);
                ffma2(acc[i][0], aa, b0);
                ffma2(acc[i][1], aa, b1);
                ffma2(acc[i][2], aa, b2);
                ffma2(acc[i][3], aa, b3);
            }
        }
        __syncthreads();
    }

    float* op = part + (size_t)ks * TD * Dm;
#pragma unroll
    for (int i = 0; i < 4; i++) {
        int q = q0 + ty * 4 + i;
        float* orow = op + (size_t)(b * Ssz + q) * Dm + h * HDm + tx * 8;
        float2 p0 = unpack2(acc[i][0]), p1 = unpack2(acc[i][1]);
        float2 p2 = unpack2(acc[i][2]), p3 = unpack2(acc[i][3]);
        *(float4*)(orow)     = make_float4(p0.x, p0.y, p1.x, p1.y);
        *(float4*)(orow + 4) = make_float4(p2.x, p2.y, p3.x, p3.y);
    }
}

// ================= pv partial reduce =================
__global__ void pvreduce_kernel(const float* __restrict__ part, float* __restrict__ O) {
    int i = blockIdx.x * blockDim.x + threadIdx.x;
    if (i >= TD * Dm) return;
    int t = i / Dm;
    int q = t % Ssz;
    int q0 = q & ~127;
    int ns = (q0 + 127) / 256 + 1;
    float s = part[i];
    if (ns > 1) s += part[(size_t)TD * Dm + i];
    if (ns > 2) s += part[2 * (size_t)TD * Dm + i];
    if (ns > 3) s += part[3 * (size_t)TD * Dm + i];
    O[i] = s;
}

// ================= fp32 FFMA2 GEMM (NN), BK=32, CTA 128x128 =================
// epi 0: bias | 1: bias+gelu(exact)
#define GEMM_SMEM_128 (3 * (128 * 36 + 32 * 128) * 4)
__global__ void __launch_bounds__(256, 2)
gemm_f32(const float* __restrict__ A, const float* __restrict__ B,
         const float* __restrict__ bias, float* __restrict__ C,
         int M, int N, int K, int epi) {
    constexpr int ASZF = 128 * 36;
    constexpr int BSZF = 32 * 128;
    extern __shared__ float sm[];
    float* as_ = sm;
    float* bs_ = sm + 3 * ASZF;
    const uint32_t sbA = smem_u32(sm);
    const uint32_t sbB = sbA + 3 * ASZF * 4;
    const int tid = threadIdx.x;
    const int tx = tid & 15, ty = tid >> 4;
    const int m0 = blockIdx.x * 128;
    const int n0 = blockIdx.y * 128;

    u64t acc[8][4];
#pragma unroll
    for (int i = 0; i < 8; i++)
#pragma unroll
        for (int j = 0; j < 4; j++) acc[i][j] = 0ULL;

    const int NC = K / BK;
    const float* gA = A + (size_t)m0 * K;
    const float* gB = B + n0;

    auto issueA = [&](int kc, int buf) {
        uint32_t base = sbA + buf * ASZF * 4;
        int k0 = kc * BK;
#pragma unroll
        for (int p = 0; p < 4; p++) {
            int idx = p * 256 + tid;
            int r = idx >> 3, c4 = idx & 7;
            CP_ASYNC16(base + (uint32_t)(r * 36 + c4 * 4) * 4,
                       gA + (size_t)r * K + k0 + c4 * 4);
        }
    };
    auto issueB = [&](int kc, int buf) {
        uint32_t base = sbB + buf * BSZF * 4;
        int k0 = kc * BK;
#pragma unroll
        for (int p = 0; p < 4; p++) {
            int idx = p * 256 + tid;
            int r = idx >> 5, c4 = idx & 31;
            CP_ASYNC16(base + (uint32_t)(r * 128 + c4 * 4) * 4,
                       gB + (size_t)(k0 + r) * N + c4 * 4);
        }
    };

    auto compute = [&](int buf) {
        const float* Ab = as_ + buf * ASZF;
        const float* Bb = bs_ + buf * BSZF;
#pragma unroll 8
        for (int h = 0; h < 16; h++) {
            float2 a2[8];
#pragma unroll
            for (int i = 0; i < 8; i++)
                a2[i] = *(const float2*)(Ab + (ty * 8 + i) * 36 + h * 2);
#pragma unroll
            for (int k2 = 0; k2 < 2; k2++) {
                const float* brow = Bb + (h * 2 + k2) * 128 + tx * 8;
                u64t b0 = *(const u64t*)(brow);
                u64t b1 = *(const u64t*)(brow + 2);
                u64t b2 = *(const u64t*)(brow + 4);
                u64t b3 = *(const u64t*)(brow + 6);
#pragma unroll
                for (int i = 0; i < 8; i++) {
                    u64t aa = splat2(k2 ? a2[i].y : a2[i].x);
                    ffma2(acc[i][0], aa, b0);
                    ffma2(acc[i][1], aa, b1);
                    ffma2(acc[i][2], aa, b2);
                    ffma2(acc[i][3], aa, b3);
                }
            }
        }
    };

    issueA(0, 0); issueB(0, 0); CP_COMMIT();
    issueA(1, 1); issueB(1, 1); CP_COMMIT();
    for (int cc = 0; cc < NC; cc++) {
        if (cc + 1 < NC) { CP_WAIT(1); } else { CP_WAIT(0); }
        __syncthreads();
        if (cc + 2 < NC) {
            int nb = (cc + 2) % 3;
            issueA(cc + 2, nb); issueB(cc + 2, nb); CP_COMMIT();
        }
        compute(cc % 3);
    }

    const int ncol = n0 + tx * 8;
    float4 bb0 = *(const float4*)(bias + ncol);
    float4 bb1 = *(const float4*)(bias + ncol + 4);
#pragma unroll
    for (int i = 0; i < 8; i++) {
        int m = m0 + ty * 8 + i;
        size_t off = (size_t)m * N + ncol;
        float o[8];
        float2 p;
        p = unpack2(acc[i][0]); o[0] = p.x + bb0.x; o[1] = p.y + bb0.y;
        p = unpack2(acc[i][1]); o[2] = p.x + bb0.z; o[3] = p.y + bb0.w;
        p = unpack2(acc[i][2]); o[4] = p.x + bb1.x; o[5] = p.y + bb1.y;
        p = unpack2(acc[i][3]); o[6] = p.x + bb1.z; o[7] = p.y + bb1.w;
        if (epi == 1) {
#pragma unroll
            for (int j = 0; j < 8; j++) {
                float g = o[j];
                o[j] = 0.5f * g * (1.0f + erff(g * 0.70710678118654752f));
            }
        }
        *(float4*)(C + off)     = make_float4(o[0], o[1], o[2], o[3]);
        *(float4*)(C + off + 4) = make_float4(o[4], o[5], o[6], o[7]);
    }
}

// ================= split-K GEMM partial: raw slab output =================
// grid (Mtiles, Ntiles, 3); slab ks covers K rows [ks*KS, (ks+1)*KS)
__global__ void __launch_bounds__(256, 2)
gemm_pk(const float* __restrict__ A, const float* __restrict__ B,
        float* __restrict__ Part, int M, int N, int K, int KS) {
    constexpr int ASZF = 128 * 36;
    constexpr int BSZF = 32 * 128;
    extern __shared__ float sm[];
    float* as_ = sm;
    float* bs_ = sm + 3 * ASZF;
    const uint32_t sbA = smem_u32(sm);
    const uint32_t sbB = sbA + 3 * ASZF * 4;
    const int tid = threadIdx.x;
    const int tx = tid & 15, ty = tid >> 4;
    const int m0 = blockIdx.x * 128;
    const int n0 = blockIdx.y * 128;
    const int ks = blockIdx.z;
    const int kbeg = ks * KS;

    u64t acc[8][4];
#pragma unroll
    for (int i = 0; i < 8; i++)
#pragma unroll
        for (int j = 0; j < 4; j++) acc[i][j] = 0ULL;

    const int NC = KS / BK;
    const float* gA = A + (size_t)m0 * K + kbeg;
    const float* gB = B + (size_t)kbeg * N + n0;

    auto issueA = [&](int kc, int buf) {
        uint32_t base = sbA + buf * ASZF * 4;
        int k0 = kc * BK;
#pragma unroll
        for (int p = 0; p < 4; p++) {
            int idx = p * 256 + tid;
            int r = idx >> 3, c4 = idx & 7;
            CP_ASYNC16(base + (uint32_t)(r * 36 + c4 * 4) * 4,
                       gA + (size_t)r * K + k0 + c4 * 4);
        }
    };
    auto issueB = [&](int kc, int buf) {
        uint32_t base = sbB + buf * BSZF * 4;
        int k0 = kc * BK;
#pragma unroll
        for (int p = 0; p < 4; p++) {
            int idx = p * 256 + tid;
            int r = idx >> 5, c4 = idx & 31;
            CP_ASYNC16(base + (uint32_t)(r * 128 + c4 * 4) * 4,
                       gB + (size_t)(k0 + r) * N + c4 * 4);
        }
    };

    auto compute = [&](int buf) {
        const float* Ab = as_ + buf * ASZF;
        const float* Bb = bs_ + buf * BSZF;
#pragma unroll 8
        for (int h = 0; h < 16; h++) {
            float2 a2[8];
#pragma unroll
            for (int i = 0; i < 8; i++)
                a2[i] = *(const float2*)(Ab + (ty * 8 + i) * 36 + h * 2);
#pragma unroll
            for (int k2 = 0; k2 < 2; k2++) {
                const float* brow = Bb + (h * 2 + k2) * 128 + tx * 8;
                u64t b0 = *(const u64t*)(brow);
                u64t b1 = *(const u64t*)(brow + 2);
                u64t b2 = *(const u64t*)(brow + 4);
                u64t b3 = *(const u64t*)(brow + 6);
#pragma unroll
                for (int i = 0; i < 8; i++) {
                    u64t aa = splat2(k2 ? a2[i].y : a2[i].x);
                    ffma2(acc[i][0], aa, b0);
                    ffma2(acc[i][1], aa, b1);
                    ffma2(acc[i][2], aa, b2);
                    ffma2(acc[i][3], aa, b3);
                }
            }
        }
    };

    issueA(0, 0); issueB(0, 0); CP_COMMIT();
    issueA(1, 1); issueB(1, 1); CP_COMMIT();
    for (int cc = 0; cc < NC; cc++) {
        if (cc + 1 < NC) { CP_WAIT(1); } else { CP_WAIT(0); }
        __syncthreads();
        if (cc + 2 < NC) {
            int nb = (cc + 2) % 3;
            issueA(cc + 2, nb); issueB(cc + 2, nb); CP_COMMIT();
        }
        compute(cc % 3);
    }

    float* P = Part + (size_t)ks * TD * Dm;
    const int ncol = n0 + tx * 8;
#pragma unroll
    for (int i = 0; i < 8; i++) {
        int m = m0 + ty * 8 + i;
        size_t off = (size_t)m * N + ncol;
        float2 p0 = unpack2(acc[i][0]), p1 = unpack2(acc[i][1]);
        float2 p2 = unpack2(acc[i][2]), p3 = unpack2(acc[i][3]);
        *(float4*)(P + off)     = make_float4(p0.x, p0.y, p1.x, p1.y);
        *(float4*)(P + off + 4) = make_float4(p2.x, p2.y, p3.x, p3.y);
    }
}

// ================= host orchestration =================
extern "C" void kernel_launch(void* const* d_in, const int* in_sizes, int n_in,
                              void* d_out, int out_size) {
    const int*   ids    = (const int*)  d_in[0];
    const float* amask  = (const float*)d_in[1];
    const float* wte    = (const float*)d_in[2];
    const float* wpe    = (const float*)d_in[3];
    const float* ln1_g  = (const float*)d_in[4];
    const float* ln1_b  = (const float*)d_in[5];
    const float* qkv_w  = (const float*)d_in[6];
    const float* qkv_b  = (const float*)d_in[7];
    const float* proj_w = (const float*)d_in[8];
    const float* proj_b = (const float*)d_in[9];
    const float* ln2_g  = (const float*)d_in[10];
    const float* ln2_b  = (const float*)d_in[11];
    const float* fc1_w  = (const float*)d_in[12];
    const float* fc1_b  = (const float*)d_in[13];
    const float* fc2_w  = (const float*)d_in[14];
    const float* fc2_b  = (const float*)d_in[15];
    const float* lnf_g  = (const float*)d_in[16];
    const float* lnf_b  = (const float*)d_in[17];
    const float* head_b = (const float*)d_in[18];
    float* out = (float*)d_out;

    float *x, *h, *qkv, *o, *mlp, *madd, *wteT, *S, *part, *gpart;
    cudaGetSymbolAddress((void**)&x,     g_x);
    cudaGetSymbolAddress((void**)&h,     g_h);
    cudaGetSymbolAddress((void**)&qkv,   g_qkv);
    cudaGetSymbolAddress((void**)&o,     g_o);
    cudaGetSymbolAddress((void**)&mlp,   g_mlp);
    cudaGetSymbolAddress((void**)&madd,  g_madd);
    cudaGetSymbolAddress((void**)&wteT,  g_wteT);
    cudaGetSymbolAddress((void**)&S,     g_s);
    cudaGetSymbolAddress((void**)&part,  g_part);
    cudaGetSymbolAddress((void**)&gpart, g_gpart);

    cudaFuncSetAttribute(gemm_f32,     cudaFuncAttributeMaxDynamicSharedMemorySize, GEMM_SMEM_128);
    cudaFuncSetAttribute(gemm_pk,      cudaFuncAttributeMaxDynamicSharedMemorySize, GEMM_SMEM_128);
    cudaFuncSetAttribute(score_kernel, cudaFuncAttributeMaxDynamicSharedMemorySize, SCORE_SMEM);
    cudaFuncSetAttribute(pv_kernel,    cudaFuncAttributeMaxDynamicSharedMemorySize, PV_SMEM);

    // launch order: embed(0), mask(1), ln(2), QKV gemm(3) <- ncu capture slot
    embed_kernel<<<(TD * Dm + 255) / 256, 256>>>(ids, wte, wpe, x);
    maskprep_kernel<<<(TD + 255) / 256, 256>>>(amask, madd);
    ln_kernel<<<TD, 256>>>(x, ln1_g, ln1_b, h, 1e-6f);   // ln1 of layer 0

    for (int l = 0; l < Ln; l++) {
        // QKV: [2048,768] @ [768,2304]  grid 16x18 = 288
        gemm_f32<<<dim3(TD / 128, 3 * Dm / 128), 256, GEMM_SMEM_128>>>(
            h, qkv_w + (size_t)l * Dm * 3 * Dm, qkv_b + (size_t)l * 3 * Dm,
            qkv, TD, 3 * Dm, Dm, 0);
        // attention
        score_kernel<<<dim3(Ssz / 128, Ssz / 128, Bsz * Hn), 256, SCORE_SMEM>>>(qkv, madd, S);
        softmax_kernel<<<Bsz * Hn * Ssz, 256>>>(S);
        pv_kernel<<<dim3(Ssz / 128, Bsz * Hn, 4), 256, PV_SMEM>>>(S, qkv, part);
        pvreduce_kernel<<<(TD * Dm + 255) / 256, 256>>>(part, o);
        // proj: split-K=3, grid 16x6x3 = 288; fused reduce+bias+residual+LN2 -> x, h
        gemm_pk<<<dim3(TD / 128, Dm / 128, 3), 256, GEMM_SMEM_128>>>(
            o, proj_w + (size_t)l * Dm * Dm, gpart, TD, Dm, Dm, Dm / 3);
        redln_kernel<<<TD, 256>>>(gpart, proj_b + (size_t)l * Dm, x, x,
                                  ln2_g + l * Dm, ln2_b + l * Dm, h, 1e-6f);
        // fc1 + gelu: single pass, grid 16x24 = 384 (R10-proven config)
        gemm_f32<<<dim3(TD / 128, 4 * Dm / 128), 256, GEMM_SMEM_128>>>(
            h, fc1_w + (size_t)l * Dm * 4 * Dm, fc1_b + (size_t)l * 4 * Dm,
            mlp, TD, 4 * Dm, Dm, 1);
        // fc2: split-K=3, grid 16x6x3 = 288; fused reduce+bias+residual+LN(next) -> x, h
        gemm_pk<<<dim3(TD / 128, Dm / 128, 3), 256, GEMM_SMEM_128>>>(
            mlp, fc2_w + (size_t)l * 4 * Dm * Dm, gpart, TD, Dm, 4 * Dm, 4 * Dm / 3);
        if (l + 1 < Ln) {
            redln_kernel<<<TD, 256>>>(gpart, fc2_b + (size_t)l * Dm, x, x,
                                      ln1_g + (l + 1) * Dm, ln1_b + (l + 1) * Dm, h, 1e-6f);
        } else {
            redln_kernel<<<TD, 256>>>(gpart, fc2_b + (size_t)l * Dm, x, x,
                                      lnf_g, lnf_b, h, 1e-5f);   // final LN
        }
    }

    transpose_wte<<<dim3(Vv / 32, Dm / 32), dim3(32, 8)>>>(wte, wteT);

    // LM head: [2048,768] @ wteT[768,50304]  grid 16x393 = 6288
    gemm_f32<<<dim3(TD / 128, Vv / 128), 256, GEMM_SMEM_128>>>(
        h, wteT, head_b, out, TD, Vv, Dm, 0);
}

// round 13
// speedup vs baseline: 1.0273x; 1.0108x over previous
#include <cuda_runtime.h>
#include <math.h>
#include <stdint.h>

#define Bsz 2
#define Ssz 1024
#define Dm  768
#define Hn  12
#define HDm 64
#define Ln  12
#define Vv  50304
#define TD  (Bsz*Ssz)   /* 2048 rows */
#define BK  32

typedef unsigned long long u64t;

// ================= helpers =================
__device__ __forceinline__ uint32_t smem_u32(const void* p) {
    uint32_t a;
    asm("{ .reg .u64 t; cvta.to.shared.u64 t, %1; cvt.u32.u64 %0, t; }" : "=r"(a) : "l"(p));
    return a;
}
#define CP_ASYNC16(s, g) asm volatile("cp.async.cg.shared.global [%0], [%1], 16;" :: "r"(s), "l"(g))
#define CP_COMMIT()      asm volatile("cp.async.commit_group;" ::: "memory")
#define CP_WAIT(n)       asm volatile("cp.async.wait_group %0;" :: "n"(n) : "memory")

__device__ __forceinline__ void ffma2(u64t& acc, u64t a, u64t b) {
    asm volatile("fma.rn.f32x2 %0, %1, %2, %0;" : "+l"(acc) : "l"(a), "l"(b));
}
__device__ __forceinline__ u64t splat2(float a) {
    u64t r; asm("mov.b64 %0, {%1, %1};" : "=l"(r) : "f"(a)); return r;
}
__device__ __forceinline__ u64t pack2(float lo, float hi) {
    u64t r; asm("mov.b64 %0, {%1, %2};" : "=l"(r) : "f"(lo), "f"(hi)); return r;
}
__device__ __forceinline__ float2 unpack2(u64t v) {
    float2 f; asm("mov.b64 {%0, %1}, %2;" : "=f"(f.x), "=f"(f.y) : "l"(v)); return f;
}

// ================= scratch =================
__device__ __align__(256) float g_x   [TD * Dm];
__device__ __align__(256) float g_h   [TD * Dm];
__device__ __align__(256) float g_qkv [TD * 3 * Dm];
__device__ __align__(256) float g_o   [TD * Dm];
__device__ __align__(256) float g_mlp [TD * 4 * Dm];
__device__ __align__(256) float g_madd[TD];
__device__ __align__(256) float g_wteT[(size_t)Dm * Vv];                // [768][50304]
__device__ __align__(256) float g_s   [(size_t)Bsz * Hn * Ssz * Ssz];  // scores/probs
__device__ __align__(256) float g_part [4][TD * Dm];                   // pv k-split partials
__device__ __align__(256) float g_gpart[3][TD * Dm];                   // proj/fc2 split-K partials

// ================= wte transpose =================
__global__ void transpose_wte(const float* __restrict__ w, float* __restrict__ wt) {
    __shared__ float t[32][33];
    int v0 = blockIdx.x * 32, d0 = blockIdx.y * 32;
#pragma unroll
    for (int i = 0; i < 4; i++)
        t[threadIdx.y + i * 8][threadIdx.x] =
            w[(size_t)(v0 + threadIdx.y + i * 8) * Dm + d0 + threadIdx.x];
    __syncthreads();
#pragma unroll
    for (int i = 0; i < 4; i++)
        wt[(size_t)(d0 + threadIdx.y + i * 8) * Vv + v0 + threadIdx.x] =
            t[threadIdx.x][threadIdx.y + i * 8];
}

// ================= embedding / mask =================
__global__ void embed_kernel(const int* __restrict__ ids, const float* __restrict__ wte,
                             const float* __restrict__ wpe, float* __restrict__ x) {
    int i = blockIdx.x * blockDim.x + threadIdx.x;
    if (i >= TD * Dm) return;
    int d = i % Dm, t = i / Dm, s = t % Ssz;
    x[i] = wte[(size_t)ids[t] * Dm + d] + wpe[(size_t)s * Dm + d];
}
__global__ void maskprep_kernel(const float* __restrict__ amask, float* __restrict__ madd) {
    int i = blockIdx.x * blockDim.x + threadIdx.x;
    if (i < TD) madd[i] = (1.0f - amask[i]) * -10000.0f;
}

// ================= layernorm (standalone: first ln1 only) =================
__global__ void ln_kernel(const float* __restrict__ x, const float* __restrict__ g,
                          const float* __restrict__ b, float* __restrict__ y, float eps) {
    int row = blockIdx.x, tid = threadIdx.x;
    const float* xr = x + (size_t)row * Dm;
    float v0 = xr[tid], v1 = xr[tid + 256], v2 = xr[tid + 512];
    __shared__ float red[256];
    red[tid] = v0 + v1 + v2;
    __syncthreads();
    for (int o = 128; o > 0; o >>= 1) { if (tid < o) red[tid] += red[tid + o]; __syncthreads(); }
    float mu = red[0] * (1.0f / Dm);
    __syncthreads();
    float d0 = v0 - mu, d1 = v1 - mu, d2 = v2 - mu;
    red[tid] = d0 * d0 + d1 * d1 + d2 * d2;
    __syncthreads();
    for (int o = 128; o > 0; o >>= 1) { if (tid < o) red[tid] += red[tid + o]; __syncthreads(); }
    float rstd = rsqrtf(red[0] * (1.0f / Dm) + eps);
    float* yr = y + (size_t)row * Dm;
    yr[tid]       = d0 * rstd * g[tid]       + b[tid];
    yr[tid + 256] = d1 * rstd * g[tid + 256] + b[tid + 256];
    yr[tid + 512] = d2 * rstd * g[tid + 512] + b[tid + 512];
}

// ========= fused: x = p0+p1+p2 + bias + res ;  h = LN(x; g,b,eps) =========
__global__ void redln_kernel(const float* __restrict__ Part, const float* __restrict__ bias,
                             const float* __restrict__ res, float* __restrict__ x,
                             const float* __restrict__ g, const float* __restrict__ b,
                             float* __restrict__ h, float eps) {
    int row = blockIdx.x, tid = threadIdx.x;
    size_t base = (size_t)row * Dm;
    float v[3];
#pragma unroll
    for (int j = 0; j < 3; j++) {
        int c = tid + j * 256;
        size_t idx = base + c;
        float s = ((Part[idx] + Part[(size_t)TD * Dm + idx]) + Part[2 * (size_t)TD * Dm + idx])
                  + bias[c] + res[idx];
        x[idx] = s;
        v[j] = s;
    }
    __shared__ float red[256];
    red[tid] = v[0] + v[1] + v[2];
    __syncthreads();
    for (int o = 128; o > 0; o >>= 1) { if (tid < o) red[tid] += red[tid + o]; __syncthreads(); }
    float mu = red[0] * (1.0f / Dm);
    __syncthreads();
    float d0 = v[0] - mu, d1 = v[1] - mu, d2 = v[2] - mu;
    red[tid] = d0 * d0 + d1 * d1 + d2 * d2;
    __syncthreads();
    for (int o = 128; o > 0; o >>= 1) { if (tid < o) red[tid] += red[tid + o]; __syncthreads(); }
    float rstd = rsqrtf(red[0] * (1.0f / Dm) + eps);
    float* hr = h + base;
    hr[tid]       = d0 * rstd * g[tid]       + b[tid];
    hr[tid + 256] = d1 * rstd * g[tid + 256] + b[tid + 256];
    hr[tid + 512] = d2 * rstd * g[tid + 512] + b[tid + 512];
}

// ================= attention: score GEMM S = Q K^T/8 (+mask) =================
// Masked tiles (ktile > qtile) are skipped entirely: softmax reads only k <= q.
#define SPAD 68
#define SCORE_SMEM (2 * 128 * SPAD * 4)
__global__ void __launch_bounds__(256)
score_kernel(const float* __restrict__ qkv, const float* __restrict__ madd,
             float* __restrict__ S) {
    if (blockIdx.y > blockIdx.x) return;   // fully causal-masked tile: never read downstream
    int bh = blockIdx.z, b = bh / Hn, h = bh % Hn;
    int q0 = blockIdx.x * 128, k0 = blockIdx.y * 128;
    int tid = threadIdx.x, tx = tid & 15, ty = tid >> 4;

    extern __shared__ float sc_sm[];
    float* Qs = sc_sm;
    float* Ks = sc_sm + 128 * SPAD;
#pragma unroll
    for (int it = 0; it < 8; it++) {
        int idx = it * 256 + tid;
        int r = idx >> 4, c4 = idx & 15;
        float4 vq = *(const float4*)(qkv + (size_t)(b * Ssz + q0 + r) * (3 * Dm) + h * 3 * HDm + c4 * 4);
        *(float4*)(Qs + r * SPAD + c4 * 4) = vq;
        float4 vk = *(const float4*)(qkv + (size_t)(b * Ssz + k0 + r) * (3 * Dm) + h * 3 * HDm + HDm + c4 * 4);
        *(float4*)(Ks + r * SPAD + c4 * 4) = vk;
    }
    __syncthreads();

    u64t acc[8][4];
#pragma unroll
    for (int i = 0; i < 8; i++)
#pragma unroll
        for (int p = 0; p < 4; p++) acc[i][p] = 0ULL;

#pragma unroll 4
    for (int d = 0; d < HDm; d++) {
        float bv[8];
#pragma unroll
        for (int j = 0; j < 8; j++) bv[j] = Ks[(tx + 16 * j) * SPAD + d];
        u64t bp[4];
#pragma unroll
        for (int p = 0; p < 4; p++) bp[p] = pack2(bv[2 * p], bv[2 * p + 1]);
#pragma unroll
        for (int i = 0; i < 8; i++) {
            u64t aa = splat2(Qs[(ty * 8 + i) * SPAD + d]);
#pragma unroll
            for (int p = 0; p < 4; p++) ffma2(acc[i][p], aa, bp[p]);
        }
    }

    float ma[8];
#pragma unroll
    for (int j = 0; j < 8; j++) ma[j] = madd[b * Ssz + k0 + tx + 16 * j];
#pragma unroll
    for (int i = 0; i < 8; i++) {
        int q = q0 + ty * 8 + i;
        float* srow = S + ((size_t)bh * Ssz + q) * Ssz + k0;
#pragma unroll
        for (int p = 0; p < 4; p++) {
            float2 v = unpack2(acc[i][p]);
            int j0 = 2 * p, j1 = 2 * p + 1;
            int kg0 = k0 + tx + 16 * j0, kg1 = k0 + tx + 16 * j1;
            srow[tx + 16 * j0] = (kg0 <= q) ? v.x * 0.125f + ma[j0] : -10000.0f + ma[j0];
            srow[tx + 16 * j1] = (kg1 <= q) ? v.y * 0.125f + ma[j1] : -10000.0f + ma[j1];
        }
    }
}

// ================= attention: prefix softmax in place =================
// Reads only k <= q (masked terms contribute exact fp32 zeros in the reference).
// Zero-fills (q, kend) where kend = ((q>>8)+1)*256 — the region pv's slabs read.
__global__ void __launch_bounds__(256)
softmax_kernel(float* __restrict__ S) {
    size_t row = blockIdx.x;
    int q = (int)(row & (Ssz - 1));
    float* r = S + row * Ssz;
    int tid = threadIdx.x;
    int idx = tid * 4;
    __shared__ float red[256];

    float4 v = make_float4(0.f, 0.f, 0.f, 0.f);
    bool load = (idx <= q);
    float lmax = -1e30f;
    if (load) {
        v = *(float4*)(r + idx);
        lmax = v.x;
        if (idx + 1 <= q) lmax = fmaxf(lmax, v.y);
        if (idx + 2 <= q) lmax = fmaxf(lmax, v.z);
        if (idx + 3 <= q) lmax = fmaxf(lmax, v.w);
    }
    red[tid] = lmax;
    __syncthreads();
    for (int o = 128; o > 0; o >>= 1) { if (tid < o) red[tid] = fmaxf(red[tid], red[tid + o]); __syncthreads(); }
    float mx = red[0];
    __syncthreads();

    float e0 = 0.f, e1 = 0.f, e2 = 0.f, e3 = 0.f;
    if (load) {
        e0 = __expf(v.x - mx);
        e1 = (idx + 1 <= q) ? __expf(v.y - mx) : 0.f;
        e2 = (idx + 2 <= q) ? __expf(v.z - mx) : 0.f;
        e3 = (idx + 3 <= q) ? __expf(v.w - mx) : 0.f;
    }
    red[tid] = e0 + e1 + e2 + e3;
    __syncthreads();
    for (int o = 128; o > 0; o >>= 1) { if (tid < o) red[tid] += red[tid + o]; __syncthreads(); }
    float inv = 1.0f / red[0];

    int kend = ((q >> 8) + 1) << 8;
    if (idx < kend) {
        float4 w;
        w.x = (idx     <= q) ? e0 * inv : 0.f;
        w.y = (idx + 1 <= q) ? e1 * inv : 0.f;
        w.z = (idx + 2 <= q) ? e2 * inv : 0.f;
        w.w = (idx + 3 <= q) ? e3 * inv : 0.f;
        *(float4*)(r + idx) = w;
    }
}

// ================= attention: O_partial = P slab @ V slab =================
#define PPAD 36
#define PS_FLOATS (128 * PPAD)
#define VS_FLOATS (32 * 64)
#define PV_SMEM (2 * (PS_FLOATS + VS_FLOATS) * 4)
__global__ void __launch_bounds__(256)
pv_kernel(const float* __restrict__ P, const float* __restrict__ qkv,
          float* __restrict__ part) {
    int bh = blockIdx.y, b = bh / Hn, h = bh % Hn;
    int q0 = blockIdx.x * 128;
    int ks = blockIdx.z;
    int kbase = ks * 256;
    if (kbase > q0 + 127) return;
    int tid = threadIdx.x, tx = tid & 7, ty = tid >> 3;

    extern __shared__ float pv_sm[];
    float* ps = pv_sm;
    float* vs = pv_sm + 2 * PS_FLOATS;
    const uint32_t sbP = smem_u32(pv_sm);
    const uint32_t sbV = sbP + 2 * PS_FLOATS * 4;

    const float* Pg = P + (size_t)bh * Ssz * Ssz;

    auto issueP = [&](int kc, int buf) {
        uint32_t base = sbP + buf * PS_FLOATS * 4;
#pragma unroll
        for (int it = 0; it < 4; it++) {
            int idx = it * 256 + tid;
            int r = idx >> 3, c4 = idx & 7;
            CP_ASYNC16(base + (uint32_t)(r * PPAD + c4 * 4) * 4,
                       Pg + (size_t)(q0 + r) * Ssz + kbase + kc * 32 + c4 * 4);
        }
    };
    auto issueV = [&](int kc, int buf) {
        uint32_t base = sbV + buf * VS_FLOATS * 4;
#pragma unroll
        for (int it = 0; it < 2; it++) {
            int idx = it * 256 + tid;
            int r = idx >> 4, c4 = idx & 15;
            CP_ASYNC16(base + (uint32_t)(r * 64 + c4 * 4) * 4,
                       qkv + (size_t)(b * Ssz + kbase + kc * 32 + r) * (3 * Dm) + h * 3 * HDm + 2 * HDm + c4 * 4);
        }
    };

    u64t acc[4][4];
#pragma unroll
    for (int i = 0; i < 4; i++)
#pragma unroll
        for (int j = 0; j < 4; j++) acc[i][j] = 0ULL;

    const int NCK = 8;
    issueP(0, 0); issueV(0, 0); CP_COMMIT();
    for (int cc = 0; cc < NCK; cc++) {
        if (cc + 1 < NCK) {
            issueP(cc + 1, (cc + 1) & 1); issueV(cc + 1, (cc + 1) & 1); CP_COMMIT();
            CP_WAIT(1);
        } else {
            CP_WAIT(0);
        }
        __syncthreads();
        const float* Pb = ps + (cc & 1) * PS_FLOATS;
        const float* Vb = vs + (cc & 1) * VS_FLOATS;
#pragma unroll 4
        for (int k = 0; k < 32; k++) {
            const float* vrow = Vb + k * 64 + tx * 8;
            u64t b0 = *(const u64t*)(vrow);
            u64t b1 = *(const u64t*)(vrow + 2);
            u64t b2 = *(const u64t*)(vrow + 4);
            u64t b3 = *(const u64t*)(vrow + 6);
#pragma unroll
            for (int i = 0; i < 4; i++) {
                u64t aa = splat2(Pb[(ty * 4 + i) * PPAD + k]);
                ffma2(acc[i][0], aa, b0);
                ffma2(acc[i][1], aa, b1);
                ffma2(acc[i][2], aa, b2);
                ffma2(acc[i][3], aa, b3);
            }
        }
        __syncthreads();
    }

    float* op = part + (size_t)ks * TD * Dm;
#pragma unroll
    for (int i = 0; i < 4; i++) {
        int q = q0 + ty * 4 + i;
        float* orow = op + (size_t)(b * Ssz + q) * Dm + h * HDm + tx * 8;
        float2 p0 = unpack2(acc[i][0]), p1 = unpack2(acc[i][1]);
        float2 p2 = unpack2(acc[i][2]), p3 = unpack2(acc[i][3]);
        *(float4*)(orow)     = make_float4(p0.x, p0.y, p1.x, p1.y);
        *(float4*)(orow + 4) = make_float4(p2.x, p2.y, p3.x, p3.y);
    }
}

// ================= pv partial reduce =================
__global__ void pvreduce_kernel(const float* __restrict__ part, float* __restrict__ O) {
    int i = blockIdx.x * blockDim.x + threadIdx.x;
    if (i >= TD * Dm) return;
    int t = i / Dm;
    int q = t % Ssz;
    int q0 = q & ~127;
    int ns = (q0 + 127) / 256 + 1;
    float s = part[i];
    if (ns > 1) s += part[(size_t)TD * Dm + i];
    if (ns > 2) s += part[2 * (size_t)TD * Dm + i];
    if (ns > 3) s += part[3 * (size_t)TD * Dm + i];
    O[i] = s;
}

// ================= fp32 FFMA2 GEMM (NN), BK=32, CTA 128x128 =================
// epi 0: bias | 1: bias+gelu(exact)
#define GEMM_SMEM_128 (3 * (128 * 36 + 32 * 128) * 4)
__global__ void __launch_bounds__(256, 2)
gemm_f32(const float* __restrict__ A, const float* __restrict__ B,
         const float* __restrict__ bias, float* __restrict__ C,
         int M, int N, int K, int epi) {
    constexpr int ASZF = 128 * 36;
    constexpr int BSZF = 32 * 128;
    extern __shared__ float sm[];
    float* as_ = sm;
    float* bs_ = sm + 3 * ASZF;
    const uint32_t sbA = smem_u32(sm);
    const uint32_t sbB = sbA + 3 * ASZF * 4;
    const int tid = threadIdx.x;
    const int tx = tid & 15, ty = tid >> 4;
    const int m0 = blockIdx.x * 128;
    const int n0 = blockIdx.y * 128;

    u64t acc[8][4];
#pragma unroll
    for (int i = 0; i < 8; i++)
#pragma unroll
        for (int j = 0; j < 4; j++) acc[i][j] = 0ULL;

    const int NC = K / BK;
    const float* gA = A + (size_t)m0 * K;
    const float* gB = B + n0;

    auto issueA = [&](int kc, int buf) {
        uint32_t base = sbA + buf * ASZF * 4;
        int k0 = kc * BK;
#pragma unroll
        for (int p = 0; p < 4; p++) {
            int idx = p * 256 + tid;
            int r = idx >> 3, c4 = idx & 7;
            CP_ASYNC16(base + (uint32_t)(r * 36 + c4 * 4) * 4,
                       gA + (size_t)r * K + k0 + c4 * 4);
        }
    };
    auto issueB = [&](int kc, int buf) {
        uint32_t base = sbB + buf * BSZF * 4;
        int k0 = kc * BK;
#pragma unroll
        for (int p = 0; p < 4; p++) {
            int idx = p * 256 + tid;
            int r = idx >> 5, c4 = idx & 31;
            CP_ASYNC16(base + (uint32_t)(r * 128 + c4 * 4) * 4,
                       gB + (size_t)(k0 + r) * N + c4 * 4);
        }
    };

    auto compute = [&](int buf) {
        const float* Ab = as_ + buf * ASZF;
        const float* Bb = bs_ + buf * BSZF;
#pragma unroll 8
        for (int h = 0; h < 16; h++) {
            float2 a2[8];
#pragma unroll
            for (int i = 0; i < 8; i++)
                a2[i] = *(const float2*)(Ab + (ty * 8 + i) * 36 + h * 2);
#pragma unroll
            for (int k2 = 0; k2 < 2; k2++) {
                const float* brow = Bb + (h * 2 + k2) * 128 + tx * 8;
                u64t b0 = *(const u64t*)(brow);
                u64t b1 = *(const u64t*)(brow + 2);
                u64t b2 = *(const u64t*)(brow + 4);
                u64t b3 = *(const u64t*)(brow + 6);
#pragma unroll
                for (int i = 0; i < 8; i++) {
                    u64t aa = splat2(k2 ? a2[i].y : a2[i].x);
                    ffma2(acc[i][0], aa, b0);
                    ffma2(acc[i][1], aa, b1);
                    ffma2(acc[i][2], aa, b2);
                    ffma2(acc[i][3], aa, b3);
                }
            }
        }
    };

    issueA(0, 0); issueB(0, 0); CP_COMMIT();
    issueA(1, 1); issueB(1, 1); CP_COMMIT();
    for (int cc = 0; cc < NC; cc++) {
        if (cc + 1 < NC) { CP_WAIT(1); } else { CP_WAIT(0); }
        __syncthreads();
        if (cc + 2 < NC) {
            int nb = (cc + 2) % 3;
            issueA(cc + 2, nb); issueB(cc + 2, nb); CP_COMMIT();
        }
        compute(cc % 3);
    }

    const int ncol = n0 + tx * 8;
    float4 bb0 = *(const float4*)(bias + ncol);
    float4 bb1 = *(const float4*)(bias + ncol + 4);
#pragma unroll
    for (int i = 0; i < 8; i++) {
        int m = m0 + ty * 8 + i;
        size_t off = (size_t)m * N + ncol;
        float o[8];
        float2 p;
        p = unpack2(acc[i][0]); o[0] = p.x + bb0.x; o[1] = p.y + bb0.y;
        p = unpack2(acc[i][1]); o[2] = p.x + bb0.z; o[3] = p.y + bb0.w;
        p = unpack2(acc[i][2]); o[4] = p.x + bb1.x; o[5] = p.y + bb1.y;
        p = unpack2(acc[i][3]); o[6] = p.x + bb1.z; o[7] = p.y + bb1.w;
        if (epi == 1) {
#pragma unroll
            for (int j = 0; j < 8; j++) {
                float g = o[j];
                o[j] = 0.5f * g * (1.0f + erff(g * 0.70710678118654752f));
            }
        }
        *(float4*)(C + off)     = make_float4(o[0], o[1], o[2], o[3]);
        *(float4*)(C + off + 4) = make_float4(o[4], o[5], o[6], o[7]);
    }
}

// ================= split-K GEMM partial: raw slab output =================
// grid (Mtiles, Ntiles, 3); slab ks covers K rows [ks*KS, (ks+1)*KS)
__global__ void __launch_bounds__(256, 2)
gemm_pk(const float* __restrict__ A, const float* __restrict__ B,
        float* __restrict__ Part, int M, int N, int K, int KS) {
    constexpr int ASZF = 128 * 36;
    constexpr int BSZF = 32 * 128;
    extern __shared__ float sm[];
    float* as_ = sm;
    float* bs_ = sm + 3 * ASZF;
    const uint32_t sbA = smem_u32(sm);
    const uint32_t sbB = sbA + 3 * ASZF * 4;
    const int tid = threadIdx.x;
    const int tx = tid & 15, ty = tid >> 4;
    const int m0 = blockIdx.x * 128;
    const int n0 = blockIdx.y * 128;
    const int ks = blockIdx.z;
    const int kbeg = ks * KS;

    u64t acc[8][4];
#pragma unroll
    for (int i = 0; i < 8; i++)
#pragma unroll
        for (int j = 0; j < 4; j++) acc[i][j] = 0ULL;

    const int NC = KS / BK;
    const float* gA = A + (size_t)m0 * K + kbeg;
    const float* gB = B + (size_t)kbeg * N + n0;

    auto issueA = [&](int kc, int buf) {
        uint32_t base = sbA + buf * ASZF * 4;
        int k0 = kc * BK;
#pragma unroll
        for (int p = 0; p < 4; p++) {
            int idx = p * 256 + tid;
            int r = idx >> 3, c4 = idx & 7;
            CP_ASYNC16(base + (uint32_t)(r * 36 + c4 * 4) * 4,
                       gA + (size_t)r * K + k0 + c4 * 4);
        }
    };
    auto issueB = [&](int kc, int buf) {
        uint32_t base = sbB + buf * BSZF * 4;
        int k0 = kc * BK;
#pragma unroll
        for (int p = 0; p < 4; p++) {
            int idx = p * 256 + tid;
            int r = idx >> 5, c4 = idx & 31;
            CP_ASYNC16(base + (uint32_t)(r * 128 + c4 * 4) * 4,
                       gB + (size_t)(k0 + r) * N + c4 * 4);
        }
    };

    auto compute = [&](int buf) {
        const float* Ab = as_ + buf * ASZF;
        const float* Bb = bs_ + buf * BSZF;
#pragma unroll 8
        for (int h = 0; h < 16; h++) {
            float2 a2[8];
#pragma unroll
            for (int i = 0; i < 8; i++)
                a2[i] = *(const float2*)(Ab + (ty * 8 + i) * 36 + h * 2);
#pragma unroll
            for (int k2 = 0; k2 < 2; k2++) {
                const float* brow = Bb + (h * 2 + k2) * 128 + tx * 8;
                u64t b0 = *(const u64t*)(brow);
                u64t b1 = *(const u64t*)(brow + 2);
                u64t b2 = *(const u64t*)(brow + 4);
                u64t b3 = *(const u64t*)(brow + 6);
#pragma unroll
                for (int i = 0; i < 8; i++) {
                    u64t aa = splat2(k2 ? a2[i].y : a2[i].x);
                    ffma2(acc[i][0], aa, b0);
                    ffma2(acc[i][1], aa, b1);
                    ffma2(acc[i][2], aa, b2);
                    ffma2(acc[i][3], aa, b3);
                }
            }
        }
    };

    issueA(0, 0); issueB(0, 0); CP_COMMIT();
    issueA(1, 1); issueB(1, 1); CP_COMMIT();
    for (int cc = 0; cc < NC; cc++) {
        if (cc + 1 < NC) { CP_WAIT(1); } else { CP_WAIT(0); }
        __syncthreads();
        if (cc + 2 < NC) {
            int nb = (cc + 2) % 3;
            issueA(cc + 2, nb); issueB(cc + 2, nb); CP_COMMIT();
        }
        compute(cc % 3);
    }

    float* P = Part + (size_t)ks * TD * Dm;
    const int ncol = n0 + tx * 8;
#pragma unroll
    for (int i = 0; i < 8; i++) {
        int m = m0 + ty * 8 + i;
        size_t off = (size_t)m * N + ncol;
        float2 p0 = unpack2(acc[i][0]), p1 = unpack2(acc[i][1]);
        float2 p2 = unpack2(acc[i][2]), p3 = unpack2(acc[i][3]);
        *(float4*)(P + off)     = make_float4(p0.x, p0.y, p1.x, p1.y);
        *(float4*)(P + off + 4) = make_float4(p2.x, p2.y, p3.x, p3.y);
    }
}

// ================= host orchestration =================
extern "C" void kernel_launch(void* const* d_in, const int* in_sizes, int n_in,
                              void* d_out, int out_size) {
    const int*   ids    = (const int*)  d_in[0];
    const float* amask  = (const float*)d_in[1];
    const float* wte    = (const float*)d_in[2];
    const float* wpe    = (const float*)d_in[3];
    const float* ln1_g  = (const float*)d_in[4];
    const float* ln1_b  = (const float*)d_in[5];
    const float* qkv_w  = (const float*)d_in[6];
    const float* qkv_b  = (const float*)d_in[7];
    const float* proj_w = (const float*)d_in[8];
    const float* proj_b = (const float*)d_in[9];
    const float* ln2_g  = (const float*)d_in[10];
    const float* ln2_b  = (const float*)d_in[11];
    const float* fc1_w  = (const float*)d_in[12];
    const float* fc1_b  = (const float*)d_in[13];
    const float* fc2_w  = (const float*)d_in[14];
    const float* fc2_b  = (const float*)d_in[15];
    const float* lnf_g  = (const float*)d_in[16];
    const float* lnf_b  = (const float*)d_in[17];
    const float* head_b = (const float*)d_in[18];
    float* out = (float*)d_out;

    float *x, *h, *qkv, *o, *mlp, *madd, *wteT, *S, *part, *gpart;
    cudaGetSymbolAddress((void**)&x,     g_x);
    cudaGetSymbolAddress((void**)&h,     g_h);
    cudaGetSymbolAddress((void**)&qkv,   g_qkv);
    cudaGetSymbolAddress((void**)&o,     g_o);
    cudaGetSymbolAddress((void**)&mlp,   g_mlp);
    cudaGetSymbolAddress((void**)&madd,  g_madd);
    cudaGetSymbolAddress((void**)&wteT,  g_wteT);
    cudaGetSymbolAddress((void**)&S,     g_s);
    cudaGetSymbolAddress((void**)&part,  g_part);
    cudaGetSymbolAddress((void**)&gpart, g_gpart);

    cudaFuncSetAttribute(gemm_f32,     cudaFuncAttributeMaxDynamicSharedMemorySize, GEMM_SMEM_128);
    cudaFuncSetAttribute(gemm_pk,      cudaFuncAttributeMaxDynamicSharedMemorySize, GEMM_SMEM_128);
    cudaFuncSetAttribute(score_kernel, cudaFuncAttributeMaxDynamicSharedMemorySize, SCORE_SMEM);
    cudaFuncSetAttribute(pv_kernel,    cudaFuncAttributeMaxDynamicSharedMemorySize, PV_SMEM);

    // launch order: embed(0), mask(1), ln(2), QKV gemm(3) <- ncu capture slot
    embed_kernel<<<(TD * Dm + 255) / 256, 256>>>(ids, wte, wpe, x);
    maskprep_kernel<<<(TD + 255) / 256, 256>>>(amask, madd);
    ln_kernel<<<TD, 256>>>(x, ln1_g, ln1_b, h, 1e-6f);   // ln1 of layer 0

    for (int l = 0; l < Ln; l++) {
        // QKV: [2048,768] @ [768,2304]  grid 16x18 = 288
        gemm_f32<<<dim3(TD / 128, 3 * Dm / 128), 256, GEMM_SMEM_128>>>(
            h, qkv_w + (size_t)l * Dm * 3 * Dm, qkv_b + (size_t)l * 3 * Dm,
            qkv, TD, 3 * Dm, Dm, 0);
        // attention
        score_kernel<<<dim3(Ssz / 128, Ssz / 128, Bsz * Hn), 256, SCORE_SMEM>>>(qkv, madd, S);
        softmax_kernel<<<Bsz * Hn * Ssz, 256>>>(S);
        pv_kernel<<<dim3(Ssz / 128, Bsz * Hn, 4), 256, PV_SMEM>>>(S, qkv, part);
        pvreduce_kernel<<<(TD * Dm + 255) / 256, 256>>>(part, o);
        // proj: split-K=3, grid 16x6x3 = 288; fused reduce+bias+residual+LN2 -> x, h
        gemm_pk<<<dim3(TD / 128, Dm / 128, 3), 256, GEMM_SMEM_128>>>(
            o, proj_w + (size_t)l * Dm * Dm, gpart, TD, Dm, Dm, Dm / 3);
        redln_kernel<<<TD, 256>>>(gpart, proj_b + (size_t)l * Dm, x, x,
                                  ln2_g + l * Dm, ln2_b + l * Dm, h, 1e-6f);
        // fc1 + gelu: single pass, grid 16x24 = 384
        gemm_f32<<<dim3(TD / 128, 4 * Dm / 128), 256, GEMM_SMEM_128>>>(
            h, fc1_w + (size_t)l * Dm * 4 * Dm, fc1_b + (size_t)l * 4 * Dm,
            mlp, TD, 4 * Dm, Dm, 1);
        // fc2: split-K=3, grid 16x6x3 = 288; fused reduce+bias+residual+LN(next) -> x, h
        gemm_pk<<<dim3(TD / 128, Dm / 128, 3), 256, GEMM_SMEM_128>>>(
            mlp, fc2_w + (size_t)l * 4 * Dm * Dm, gpart, TD, Dm, 4 * Dm, 4 * Dm / 3);
        if (l + 1 < Ln) {
            redln_kernel<<<TD, 256>>>(gpart, fc2_b + (size_t)l * Dm, x, x,
                                      ln1_g + (l + 1) * Dm, ln1_b + (l + 1) * Dm, h, 1e-6f);
        } else {
            redln_kernel<<<TD, 256>>>(gpart, fc2_b + (size_t)l * Dm, x, x,
                                      lnf_g, lnf_b, h, 1e-5f);   // final LN
        }
    }

    transpose_wte<<<dim3(Vv / 32, Dm / 32), dim3(32, 8)>>>(wte, wteT);

    // LM head: [2048,768] @ wteT[768,50304]  grid 16x393 = 6288
    gemm_f32<<<dim3(TD / 128, Vv / 128), 256, GEMM_SMEM_128>>>(
        h, wteT, head_b, out, TD, Vv, Dm, 0);
}

// round 14
// speedup vs baseline: 1.0323x; 1.0049x over previous
#include <cuda_runtime.h>
#include <math.h>
#include <stdint.h>

#define Bsz 2
#define Ssz 1024
#define Dm  768
#define Hn  12
#define HDm 64
#define Ln  12
#define Vv  50304
#define TD  (Bsz*Ssz)   /* 2048 rows */
#define BK  32

typedef unsigned long long u64t;

// ================= helpers =================
__device__ __forceinline__ uint32_t smem_u32(const void* p) {
    uint32_t a;
    asm("{ .reg .u64 t; cvta.to.shared.u64 t, %1; cvt.u32.u64 %0, t; }" : "=r"(a) : "l"(p));
    return a;
}
#define CP_ASYNC16(s, g) asm volatile("cp.async.cg.shared.global [%0], [%1], 16;" :: "r"(s), "l"(g))
#define CP_COMMIT()      asm volatile("cp.async.commit_group;" ::: "memory")
#define CP_WAIT(n)       asm volatile("cp.async.wait_group %0;" :: "n"(n) : "memory")

__device__ __forceinline__ void ffma2(u64t& acc, u64t a, u64t b) {
    asm volatile("fma.rn.f32x2 %0, %1, %2, %0;" : "+l"(acc) : "l"(a), "l"(b));
}
__device__ __forceinline__ u64t splat2(float a) {
    u64t r; asm("mov.b64 %0, {%1, %1};" : "=l"(r) : "f"(a)); return r;
}
__device__ __forceinline__ u64t pack2(float lo, float hi) {
    u64t r; asm("mov.b64 %0, {%1, %2};" : "=l"(r) : "f"(lo), "f"(hi)); return r;
}
__device__ __forceinline__ float2 unpack2(u64t v) {
    float2 f; asm("mov.b64 {%0, %1}, %2;" : "=f"(f.x), "=f"(f.y) : "l"(v)); return f;
}

// ================= scratch =================
__device__ __align__(256) float g_x   [TD * Dm];
__device__ __align__(256) float g_h   [TD * Dm];
__device__ __align__(256) float g_qkv [TD * 3 * Dm];
__device__ __align__(256) float g_o   [TD * Dm];
__device__ __align__(256) float g_mlp [TD * 4 * Dm];
__device__ __align__(256) float g_madd[TD];
__device__ __align__(256) float g_wteT[(size_t)Dm * Vv];                // [768][50304]
__device__ __align__(256) float g_s   [(size_t)Bsz * Hn * Ssz * Ssz];  // scores/probs
__device__ __align__(256) float g_part [4][TD * Dm];                   // pv k-split partials
__device__ __align__(256) float g_gpart[3][TD * Dm];                   // proj/fc2 split-K partials

// ================= wte transpose =================
__global__ void transpose_wte(const float* __restrict__ w, float* __restrict__ wt) {
    __shared__ float t[32][33];
    int v0 = blockIdx.x * 32, d0 = blockIdx.y * 32;
#pragma unroll
    for (int i = 0; i < 4; i++)
        t[threadIdx.y + i * 8][threadIdx.x] =
            w[(size_t)(v0 + threadIdx.y + i * 8) * Dm + d0 + threadIdx.x];
    __syncthreads();
#pragma unroll
    for (int i = 0; i < 4; i++)
        wt[(size_t)(d0 + threadIdx.y + i * 8) * Vv + v0 + threadIdx.x] =
            t[threadIdx.x][threadIdx.y + i * 8];
}

// ================= embedding / mask =================
__global__ void embed_kernel(const int* __restrict__ ids, const float* __restrict__ wte,
                             const float* __restrict__ wpe, float* __restrict__ x) {
    int i = blockIdx.x * blockDim.x + threadIdx.x;
    if (i >= TD * Dm) return;
    int d = i % Dm, t = i / Dm, s = t % Ssz;
    x[i] = wte[(size_t)ids[t] * Dm + d] + wpe[(size_t)s * Dm + d];
}
__global__ void maskprep_kernel(const float* __restrict__ amask, float* __restrict__ madd) {
    int i = blockIdx.x * blockDim.x + threadIdx.x;
    if (i < TD) madd[i] = (1.0f - amask[i]) * -10000.0f;
}

// ================= layernorm (standalone: first ln1 only) =================
__global__ void ln_kernel(const float* __restrict__ x, const float* __restrict__ g,
                          const float* __restrict__ b, float* __restrict__ y, float eps) {
    int row = blockIdx.x, tid = threadIdx.x;
    const float* xr = x + (size_t)row * Dm;
    float v0 = xr[tid], v1 = xr[tid + 256], v2 = xr[tid + 512];
    __shared__ float red[256];
    red[tid] = v0 + v1 + v2;
    __syncthreads();
    for (int o = 128; o > 0; o >>= 1) { if (tid < o) red[tid] += red[tid + o]; __syncthreads(); }
    float mu = red[0] * (1.0f / Dm);
    __syncthreads();
    float d0 = v0 - mu, d1 = v1 - mu, d2 = v2 - mu;
    red[tid] = d0 * d0 + d1 * d1 + d2 * d2;
    __syncthreads();
    for (int o = 128; o > 0; o >>= 1) { if (tid < o) red[tid] += red[tid + o]; __syncthreads(); }
    float rstd = rsqrtf(red[0] * (1.0f / Dm) + eps);
    float* yr = y + (size_t)row * Dm;
    yr[tid]       = d0 * rstd * g[tid]       + b[tid];
    yr[tid + 256] = d1 * rstd * g[tid + 256] + b[tid + 256];
    yr[tid + 512] = d2 * rstd * g[tid + 512] + b[tid + 512];
}

// ========= fused: x = p0+p1+p2 + bias + res ;  h = LN(x; g,b,eps) =========
__global__ void redln_kernel(const float* __restrict__ Part, const float* __restrict__ bias,
                             const float* __restrict__ res, float* __restrict__ x,
                             const float* __restrict__ g, const float* __restrict__ b,
                             float* __restrict__ h, float eps) {
    int row = blockIdx.x, tid = threadIdx.x;
    size_t base = (size_t)row * Dm;
    float v[3];
#pragma unroll
    for (int j = 0; j < 3; j++) {
        int c = tid + j * 256;
        size_t idx = base + c;
        float s = ((Part[idx] + Part[(size_t)TD * Dm + idx]) + Part[2 * (size_t)TD * Dm + idx])
                  + bias[c] + res[idx];
        x[idx] = s;
        v[j] = s;
    }
    __shared__ float red[256];
    red[tid] = v[0] + v[1] + v[2];
    __syncthreads();
    for (int o = 128; o > 0; o >>= 1) { if (tid < o) red[tid] += red[tid + o]; __syncthreads(); }
    float mu = red[0] * (1.0f / Dm);
    __syncthreads();
    float d0 = v[0] - mu, d1 = v[1] - mu, d2 = v[2] - mu;
    red[tid] = d0 * d0 + d1 * d1 + d2 * d2;
    __syncthreads();
    for (int o = 128; o > 0; o >>= 1) { if (tid < o) red[tid] += red[tid + o]; __syncthreads(); }
    float rstd = rsqrtf(red[0] * (1.0f / Dm) + eps);
    float* hr = h + base;
    hr[tid]       = d0 * rstd * g[tid]       + b[tid];
    hr[tid + 256] = d1 * rstd * g[tid + 256] + b[tid + 256];
    hr[tid + 512] = d2 * rstd * g[tid + 512] + b[tid + 512];
}

// ================= attention: score GEMM S = Q K^T/8 (+mask) =================
// Only k <= q entries are ever read downstream; all other stores are skipped.
#define SPAD 68
#define SCORE_SMEM (2 * 128 * SPAD * 4)
__global__ void __launch_bounds__(256)
score_kernel(const float* __restrict__ qkv, const float* __restrict__ madd,
             float* __restrict__ S) {
    if (blockIdx.y > blockIdx.x) return;   // fully causal-masked tile
    int bh = blockIdx.z, b = bh / Hn, h = bh % Hn;
    int q0 = blockIdx.x * 128, k0 = blockIdx.y * 128;
    int tid = threadIdx.x, tx = tid & 15, ty = tid >> 4;

    extern __shared__ float sc_sm[];
    float* Qs = sc_sm;
    float* Ks = sc_sm + 128 * SPAD;
#pragma unroll
    for (int it = 0; it < 8; it++) {
        int idx = it * 256 + tid;
        int r = idx >> 4, c4 = idx & 15;
        float4 vq = *(const float4*)(qkv + (size_t)(b * Ssz + q0 + r) * (3 * Dm) + h * 3 * HDm + c4 * 4);
        *(float4*)(Qs + r * SPAD + c4 * 4) = vq;
        float4 vk = *(const float4*)(qkv + (size_t)(b * Ssz + k0 + r) * (3 * Dm) + h * 3 * HDm + HDm + c4 * 4);
        *(float4*)(Ks + r * SPAD + c4 * 4) = vk;
    }
    __syncthreads();

    u64t acc[8][4];
#pragma unroll
    for (int i = 0; i < 8; i++)
#pragma unroll
        for (int p = 0; p < 4; p++) acc[i][p] = 0ULL;

#pragma unroll 4
    for (int d = 0; d < HDm; d++) {
        float bv[8];
#pragma unroll
        for (int j = 0; j < 8; j++) bv[j] = Ks[(tx + 16 * j) * SPAD + d];
        u64t bp[4];
#pragma unroll
        for (int p = 0; p < 4; p++) bp[p] = pack2(bv[2 * p], bv[2 * p + 1]);
#pragma unroll
        for (int i = 0; i < 8; i++) {
            u64t aa = splat2(Qs[(ty * 8 + i) * SPAD + d]);
#pragma unroll
            for (int p = 0; p < 4; p++) ffma2(acc[i][p], aa, bp[p]);
        }
    }

    float ma[8];
#pragma unroll
    for (int j = 0; j < 8; j++) ma[j] = madd[b * Ssz + k0 + tx + 16 * j];
#pragma unroll
    for (int i = 0; i < 8; i++) {
        int q = q0 + ty * 8 + i;
        float* srow = S + ((size_t)bh * Ssz + q) * Ssz + k0;
#pragma unroll
        for (int p = 0; p < 4; p++) {
            float2 v = unpack2(acc[i][p]);
            int j0 = 2 * p, j1 = 2 * p + 1;
            int kg0 = k0 + tx + 16 * j0, kg1 = k0 + tx + 16 * j1;
            if (kg0 <= q) srow[tx + 16 * j0] = v.x * 0.125f + ma[j0];
            if (kg1 <= q) srow[tx + 16 * j1] = v.y * 0.125f + ma[j1];
        }
    }
}

// ================= attention: prefix softmax in place =================
// Reads only k <= q; zero-fills (q, kend), kend = ((q>>8)+1)*256 (pv's read span).
__global__ void __launch_bounds__(256)
softmax_kernel(float* __restrict__ S) {
    size_t row = blockIdx.x;
    int q = (int)(row & (Ssz - 1));
    float* r = S + row * Ssz;
    int tid = threadIdx.x;
    int idx = tid * 4;
    __shared__ float red[256];

    float4 v = make_float4(0.f, 0.f, 0.f, 0.f);
    bool load = (idx <= q);
    float lmax = -1e30f;
    if (load) {
        v = *(float4*)(r + idx);
        lmax = v.x;
        if (idx + 1 <= q) lmax = fmaxf(lmax, v.y);
        if (idx + 2 <= q) lmax = fmaxf(lmax, v.z);
        if (idx + 3 <= q) lmax = fmaxf(lmax, v.w);
    }
    red[tid] = lmax;
    __syncthreads();
    for (int o = 128; o > 0; o >>= 1) { if (tid < o) red[tid] = fmaxf(red[tid], red[tid + o]); __syncthreads(); }
    float mx = red[0];
    __syncthreads();

    float e0 = 0.f, e1 = 0.f, e2 = 0.f, e3 = 0.f;
    if (load) {
        e0 = __expf(v.x - mx);
        e1 = (idx + 1 <= q) ? __expf(v.y - mx) : 0.f;
        e2 = (idx + 2 <= q) ? __expf(v.z - mx) : 0.f;
        e3 = (idx + 3 <= q) ? __expf(v.w - mx) : 0.f;
    }
    red[tid] = e0 + e1 + e2 + e3;
    __syncthreads();
    for (int o = 128; o > 0; o >>= 1) { if (tid < o) red[tid] += red[tid + o]; __syncthreads(); }
    float inv = 1.0f / red[0];

    int kend = ((q >> 8) + 1) << 8;
    if (idx < kend) {
        float4 w;
        w.x = (idx     <= q) ? e0 * inv : 0.f;
        w.y = (idx + 1 <= q) ? e1 * inv : 0.f;
        w.z = (idx + 2 <= q) ? e2 * inv : 0.f;
        w.w = (idx + 3 <= q) ? e3 * inv : 0.f;
        *(float4*)(r + idx) = w;
    }
}

// ================= attention: O_partial = P slab @ V slab =================
// Diagonal slabs clamp chunk count: P is exact zero beyond q0+127, and +=0*v is
// bitwise identity, so skipped chunks change nothing.
#define PPAD 36
#define PS_FLOATS (128 * PPAD)
#define VS_FLOATS (32 * 64)
#define PV_SMEM (2 * (PS_FLOATS + VS_FLOATS) * 4)
__global__ void __launch_bounds__(256)
pv_kernel(const float* __restrict__ P, const float* __restrict__ qkv,
          float* __restrict__ part) {
    int bh = blockIdx.y, b = bh / Hn, h = bh % Hn;
    int q0 = blockIdx.x * 128;
    int ks = blockIdx.z;
    int kbase = ks * 256;
    if (kbase > q0 + 127) return;
    int tid = threadIdx.x, tx = tid & 7, ty = tid >> 3;

    // chunks actually containing nonzero P: span = q0+128-kbase (128 or >=256)
    int span = q0 + 128 - kbase;
    const int NCK = (span >= 256) ? 8 : 4;

    extern __shared__ float pv_sm[];
    float* ps = pv_sm;
    float* vs = pv_sm + 2 * PS_FLOATS;
    const uint32_t sbP = smem_u32(pv_sm);
    const uint32_t sbV = sbP + 2 * PS_FLOATS * 4;

    const float* Pg = P + (size_t)bh * Ssz * Ssz;

    auto issueP = [&](int kc, int buf) {
        uint32_t base = sbP + buf * PS_FLOATS * 4;
#pragma unroll
        for (int it = 0; it < 4; it++) {
            int idx = it * 256 + tid;
            int r = idx >> 3, c4 = idx & 7;
            CP_ASYNC16(base + (uint32_t)(r * PPAD + c4 * 4) * 4,
                       Pg + (size_t)(q0 + r) * Ssz + kbase + kc * 32 + c4 * 4);
        }
    };
    auto issueV = [&](int kc, int buf) {
        uint32_t base = sbV + buf * VS_FLOATS * 4;
#pragma unroll
        for (int it = 0; it < 2; it++) {
            int idx = it * 256 + tid;
            int r = idx >> 4, c4 = idx & 15;
            CP_ASYNC16(base + (uint32_t)(r * 64 + c4 * 4) * 4,
                       qkv + (size_t)(b * Ssz + kbase + kc * 32 + r) * (3 * Dm) + h * 3 * HDm + 2 * HDm + c4 * 4);
        }
    };

    u64t acc[4][4];
#pragma unroll
    for (int i = 0; i < 4; i++)
#pragma unroll
        for (int j = 0; j < 4; j++) acc[i][j] = 0ULL;

    issueP(0, 0); issueV(0, 0); CP_COMMIT();
    for (int cc = 0; cc < NCK; cc++) {
        if (cc + 1 < NCK) {
            issueP(cc + 1, (cc + 1) & 1); issueV(cc + 1, (cc + 1) & 1); CP_COMMIT();
            CP_WAIT(1);
        } else {
            CP_WAIT(0);
        }
        __syncthreads();
        const float* Pb = ps + (cc & 1) * PS_FLOATS;
        const float* Vb = vs + (cc & 1) * VS_FLOATS;
#pragma unroll 4
        for (int k = 0; k < 32; k++) {
            const float* vrow = Vb + k * 64 + tx * 8;
            u64t b0 = *(const u64t*)(vrow);
            u64t b1 = *(const u64t*)(vrow + 2);
            u64t b2 = *(const u64t*)(vrow + 4);
            u64t b3 = *(const u64t*)(vrow + 6);
#pragma unroll
            for (int i = 0; i < 4; i++) {
                u64t aa = splat2(Pb[(ty * 4 + i) * PPAD + k]);
                ffma2(acc[i][0], aa, b0);
                ffma2(acc[i][1], aa, b1);
                ffma2(acc[i][2], aa, b2);
                ffma2(acc[i][3], aa, b3);
            }
        }
        __syncthreads();
    }

    float* op = part + (size_t)ks * TD * Dm;
#pragma unroll
    for (int i = 0; i < 4; i++) {
        int q = q0 + ty * 4 + i;
        float* orow = op + (size_t)(b * Ssz + q) * Dm + h * HDm + tx * 8;
        float2 p0 = unpack2(acc[i][0]), p1 = unpack2(acc[i][1]);
        float2 p2 = unpack2(acc[i][2]), p3 = unpack2(acc[i][3]);
        *(float4*)(orow)     = make_float4(p0.x, p0.y, p1.x, p1.y);
        *(float4*)(orow + 4) = make_float4(p2.x, p2.y, p3.x, p3.y);
    }
}

// ================= pv partial reduce =================
__global__ void pvreduce_kernel(const float* __restrict__ part, float* __restrict__ O) {
    int i = blockIdx.x * blockDim.x + threadIdx.x;
    if (i >= TD * Dm) return;
    int t = i / Dm;
    int q = t % Ssz;
    int q0 = q & ~127;
    int ns = (q0 + 127) / 256 + 1;
    float s = part[i];
    if (ns > 1) s += part[(size_t)TD * Dm + i];
    if (ns > 2) s += part[2 * (size_t)TD * Dm + i];
    if (ns > 3) s += part[3 * (size_t)TD * Dm + i];
    O[i] = s;
}

// ================= fp32 FFMA2 GEMM (NN), BK=32, CTA 128x128 =================
// epi 0: bias | 1: bias+gelu(exact)
#define GEMM_SMEM_128 (3 * (128 * 36 + 32 * 128) * 4)
__global__ void __launch_bounds__(256, 2)
gemm_f32(const float* __restrict__ A, const float* __restrict__ B,
         const float* __restrict__ bias, float* __restrict__ C,
         int M, int N, int K, int epi) {
    constexpr int ASZF = 128 * 36;
    constexpr int BSZF = 32 * 128;
    extern __shared__ float sm[];
    float* as_ = sm;
    float* bs_ = sm + 3 * ASZF;
    const uint32_t sbA = smem_u32(sm);
    const uint32_t sbB = sbA + 3 * ASZF * 4;
    const int tid = threadIdx.x;
    const int tx = tid & 15, ty = tid >> 4;
    const int m0 = blockIdx.x * 128;
    const int n0 = blockIdx.y * 128;

    u64t acc[8][4];
#pragma unroll
    for (int i = 0; i < 8; i++)
#pragma unroll
        for (int j = 0; j < 4; j++) acc[i][j] = 0ULL;

    const int NC = K / BK;
    const float* gA = A + (size_t)m0 * K;
    const float* gB = B + n0;

    auto issueA = [&](int kc, int buf) {
        uint32_t base = sbA + buf * ASZF * 4;
        int k0 = kc * BK;
#pragma unroll
        for (int p = 0; p < 4; p++) {
            int idx = p * 256 + tid;
            int r = idx >> 3, c4 = idx & 7;
            CP_ASYNC16(base + (uint32_t)(r * 36 + c4 * 4) * 4,
                       gA + (size_t)r * K + k0 + c4 * 4);
        }
    };
    auto issueB = [&](int kc, int buf) {
        uint32_t base = sbB + buf * BSZF * 4;
        int k0 = kc * BK;
#pragma unroll
        for (int p = 0; p < 4; p++) {
            int idx = p * 256 + tid;
            int r = idx >> 5, c4 = idx & 31;
            CP_ASYNC16(base + (uint32_t)(r * 128 + c4 * 4) * 4,
                       gB + (size_t)(k0 + r) * N + c4 * 4);
        }
    };

    auto compute = [&](int buf) {
        const float* Ab = as_ + buf * ASZF;
        const float* Bb = bs_ + buf * BSZF;
#pragma unroll 8
        for (int h = 0; h < 16; h++) {
            float2 a2[8];
#pragma unroll
            for (int i = 0; i < 8; i++)
                a2[i] = *(const float2*)(Ab + (ty * 8 + i) * 36 + h * 2);
#pragma unroll
            for (int k2 = 0; k2 < 2; k2++) {
                const float* brow = Bb + (h * 2 + k2) * 128 + tx * 8;
                u64t b0 = *(const u64t*)(brow);
                u64t b1 = *(const u64t*)(brow + 2);
                u64t b2 = *(const u64t*)(brow + 4);
                u64t b3 = *(const u64t*)(brow + 6);
#pragma unroll
                for (int i = 0; i < 8; i++) {
                    u64t aa = splat2(k2 ? a2[i].y : a2[i].x);
                    ffma2(acc[i][0], aa, b0);
                    ffma2(acc[i][1], aa, b1);
                    ffma2(acc[i][2], aa, b2);
                    ffma2(acc[i][3], aa, b3);
                }
            }
        }
    };

    issueA(0, 0); issueB(0, 0); CP_COMMIT();
    issueA(1, 1); issueB(1, 1); CP_COMMIT();
    for (int cc = 0; cc < NC; cc++) {
        if (cc + 1 < NC) { CP_WAIT(1); } else { CP_WAIT(0); }
        __syncthreads();
        if (cc + 2 < NC) {
            int nb = (cc + 2) % 3;
            issueA(cc + 2, nb); issueB(cc + 2, nb); CP_COMMIT();
        }
        compute(cc % 3);
    }

    const int ncol = n0 + tx * 8;
    float4 bb0 = *(const float4*)(bias + ncol);
    float4 bb1 = *(const float4*)(bias + ncol + 4);
#pragma unroll
    for (int i = 0; i < 8; i++) {
        int m = m0 + ty * 8 + i;
        size_t off = (size_t)m * N + ncol;
        float o[8];
        float2 p;
        p = unpack2(acc[i][0]); o[0] = p.x + bb0.x; o[1] = p.y + bb0.y;
        p = unpack2(acc[i][1]); o[2] = p.x + bb0.z; o[3] = p.y + bb0.w;
        p = unpack2(acc[i][2]); o[4] = p.x + bb1.x; o[5] = p.y + bb1.y;
        p = unpack2(acc[i][3]); o[6] = p.x + bb1.z; o[7] = p.y + bb1.w;
        if (epi == 1) {
#pragma unroll
            for (int j = 0; j < 8; j++) {
                float g = o[j];
                o[j] = 0.5f * g * (1.0f + erff(g * 0.70710678118654752f));
            }
        }
        *(float4*)(C + off)     = make_float4(o[0], o[1], o[2], o[3]);
        *(float4*)(C + off + 4) = make_float4(o[4], o[5], o[6], o[7]);
    }
}

// ================= split-K GEMM partial: raw slab output =================
__global__ void __launch_bounds__(256, 2)
gemm_pk(const float* __restrict__ A, const float* __restrict__ B,
        float* __restrict__ Part, int M, int N, int K, int KS) {
    constexpr int ASZF = 128 * 36;
    constexpr int BSZF = 32 * 128;
    extern __shared__ float sm[];
    float* as_ = sm;
    float* bs_ = sm + 3 * ASZF;
    const uint32_t sbA = smem_u32(sm);
    const uint32_t sbB = sbA + 3 * ASZF * 4;
    const int tid = threadIdx.x;
    const int tx = tid & 15, ty = tid >> 4;
    const int m0 = blockIdx.x * 128;
    const int n0 = blockIdx.y * 128;
    const int ks = blockIdx.z;
    const int kbeg = ks * KS;

    u64t acc[8][4];
#pragma unroll
    for (int i = 0; i < 8; i++)
#pragma unroll
        for (int j = 0; j < 4; j++) acc[i][j] = 0ULL;

    const int NC = KS / BK;
    const float* gA = A + (size_t)m0 * K + kbeg;
    const float* gB = B + (size_t)kbeg * N + n0;

    auto issueA = [&](int kc, int buf) {
        uint32_t base = sbA + buf * ASZF * 4;
        int k0 = kc * BK;
#pragma unroll
        for (int p = 0; p < 4; p++) {
            int idx = p * 256 + tid;
            int r = idx >> 3, c4 = idx & 7;
            CP_ASYNC16(base + (uint32_t)(r * 36 + c4 * 4) * 4,
                       gA + (size_t)r * K + k0 + c4 * 4);
        }
    };
    auto issueB = [&](int kc, int buf) {
        uint32_t base = sbB + buf * BSZF * 4;
        int k0 = kc * BK;
#pragma unroll
        for (int p = 0; p < 4; p++) {
            int idx = p * 256 + tid;
            int r = idx >> 5, c4 = idx & 31;
            CP_ASYNC16(base + (uint32_t)(r * 128 + c4 * 4) * 4,
                       gB + (size_t)(k0 + r) * N + c4 * 4);
        }
    };

    auto compute = [&](int buf) {
        const float* Ab = as_ + buf * ASZF;
        const float* Bb = bs_ + buf * BSZF;
#pragma unroll 8
        for (int h = 0; h < 16; h++) {
            float2 a2[8];
#pragma unroll
            for (int i = 0; i < 8; i++)
                a2[i] = *(const float2*)(Ab + (ty * 8 + i) * 36 + h * 2);
#pragma unroll
            for (int k2 = 0; k2 < 2; k2++) {
                const float* brow = Bb + (h * 2 + k2) * 128 + tx * 8;
                u64t b0 = *(const u64t*)(brow);
                u64t b1 = *(const u64t*)(brow + 2);
                u64t b2 = *(const u64t*)(brow + 4);
                u64t b3 = *(const u64t*)(brow + 6);
#pragma unroll
                for (int i = 0; i < 8; i++) {
                    u64t aa = splat2(k2 ? a2[i].y : a2[i].x);
                    ffma2(acc[i][0], aa, b0);
                    ffma2(acc[i][1], aa, b1);
                    ffma2(acc[i][2], aa, b2);
                    ffma2(acc[i][3], aa, b3);
                }
            }
        }
    };

    issueA(0, 0); issueB(0, 0); CP_COMMIT();
    issueA(1, 1); issueB(1, 1); CP_COMMIT();
    for (int cc = 0; cc < NC; cc++) {
        if (cc + 1 < NC) { CP_WAIT(1); } else { CP_WAIT(0); }
        __syncthreads();
        if (cc + 2 < NC) {
            int nb = (cc + 2) % 3;
            issueA(cc + 2, nb); issueB(cc + 2, nb); CP_COMMIT();
        }
        compute(cc % 3);
    }

    float* P = Part + (size_t)ks * TD * Dm;
    const int ncol = n0 + tx * 8;
#pragma unroll
    for (int i = 0; i < 8; i++) {
        int m = m0 + ty * 8 + i;
        size_t off = (size_t)m * N + ncol;
        float2 p0 = unpack2(acc[i][0]), p1 = unpack2(acc[i][1]);
        float2 p2 = unpack2(acc[i][2]), p3 = unpack2(acc[i][3]);
        *(float4*)(P + off)     = make_float4(p0.x, p0.y, p1.x, p1.y);
        *(float4*)(P + off + 4) = make_float4(p2.x, p2.y, p3.x, p3.y);
    }
}

// ================= host orchestration =================
extern "C" void kernel_launch(void* const* d_in, const int* in_sizes, int n_in,
                              void* d_out, int out_size) {
    const int*   ids    = (const int*)  d_in[0];
    const float* amask  = (const float*)d_in[1];
    const float* wte    = (const float*)d_in[2];
    const float* wpe    = (const float*)d_in[3];
    const float* ln1_g  = (const float*)d_in[4];
    const float* ln1_b  = (const float*)d_in[5];
    const float* qkv_w  = (const float*)d_in[6];
    const float* qkv_b  = (const float*)d_in[7];
    const float* proj_w = (const float*)d_in[8];
    const float* proj_b = (const float*)d_in[9];
    const float* ln2_g  = (const float*)d_in[10];
    const float* ln2_b  = (const float*)d_in[11];
    const float* fc1_w  = (const float*)d_in[12];
    const float* fc1_b  = (const float*)d_in[13];
    const float* fc2_w  = (const float*)d_in[14];
    const float* fc2_b  = (const float*)d_in[15];
    const float* lnf_g  = (const float*)d_in[16];
    const float* lnf_b  = (const float*)d_in[17];
    const float* head_b = (const float*)d_in[18];
    float* out = (float*)d_out;

    float *x, *h, *qkv, *o, *mlp, *madd, *wteT, *S, *part, *gpart;
    cudaGetSymbolAddress((void**)&x,     g_x);
    cudaGetSymbolAddress((void**)&h,     g_h);
    cudaGetSymbolAddress((void**)&qkv,   g_qkv);
    cudaGetSymbolAddress((void**)&o,     g_o);
    cudaGetSymbolAddress((void**)&mlp,   g_mlp);
    cudaGetSymbolAddress((void**)&madd,  g_madd);
    cudaGetSymbolAddress((void**)&wteT,  g_wteT);
    cudaGetSymbolAddress((void**)&S,     g_s);
    cudaGetSymbolAddress((void**)&part,  g_part);
    cudaGetSymbolAddress((void**)&gpart, g_gpart);

    cudaFuncSetAttribute(gemm_f32,     cudaFuncAttributeMaxDynamicSharedMemorySize, GEMM_SMEM_128);
    cudaFuncSetAttribute(gemm_pk,      cudaFuncAttributeMaxDynamicSharedMemorySize, GEMM_SMEM_128);
    cudaFuncSetAttribute(score_kernel, cudaFuncAttributeMaxDynamicSharedMemorySize, SCORE_SMEM);
    cudaFuncSetAttribute(pv_kernel,    cudaFuncAttributeMaxDynamicSharedMemorySize, PV_SMEM);

    // launch order: embed(0), mask(1), ln(2), QKV gemm(3) <- ncu capture slot
    embed_kernel<<<(TD * Dm + 255) / 256, 256>>>(ids, wte, wpe, x);
    maskprep_kernel<<<(TD + 255) / 256, 256>>>(amask, madd);
    ln_kernel<<<TD, 256>>>(x, ln1_g, ln1_b, h, 1e-6f);   // ln1 of layer 0

    for (int l = 0; l < Ln; l++) {
        // QKV: [2048,768] @ [768,2304]  grid 16x18 = 288
        gemm_f32<<<dim3(TD / 128, 3 * Dm / 128), 256, GEMM_SMEM_128>>>(
            h, qkv_w + (size_t)l * Dm * 3 * Dm, qkv_b + (size_t)l * 3 * Dm,
            qkv, TD, 3 * Dm, Dm, 0);
        // attention
        score_kernel<<<dim3(Ssz / 128, Ssz / 128, Bsz * Hn), 256, SCORE_SMEM>>>(qkv, madd, S);
        softmax_kernel<<<Bsz * Hn * Ssz, 256>>>(S);
        pv_kernel<<<dim3(Ssz / 128, Bsz * Hn, 4), 256, PV_SMEM>>>(S, qkv, part);
        pvreduce_kernel<<<(TD * Dm + 255) / 256, 256>>>(part, o);
        // proj: split-K=3, grid 16x6x3 = 288; fused reduce+bias+residual+LN2 -> x, h
        gemm_pk<<<dim3(TD / 128, Dm / 128, 3), 256, GEMM_SMEM_128>>>(
            o, proj_w + (size_t)l * Dm * Dm, gpart, TD, Dm, Dm, Dm / 3);
        redln_kernel<<<TD, 256>>>(gpart, proj_b + (size_t)l * Dm, x, x,
                                  ln2_g + l * Dm, ln2_b + l * Dm, h, 1e-6f);
        // fc1 + gelu: single pass, grid 16x24 = 384
        gemm_f32<<<dim3(TD / 128, 4 * Dm / 128), 256, GEMM_SMEM_128>>>(
            h, fc1_w + (size_t)l * Dm * 4 * Dm, fc1_b + (size_t)l * 4 * Dm,
            mlp, TD, 4 * Dm, Dm, 1);
        // fc2: split-K=3, grid 16x6x3 = 288; fused reduce+bias+residual+LN(next) -> x, h
        gemm_pk<<<dim3(TD / 128, Dm / 128, 3), 256, GEMM_SMEM_128>>>(
            mlp, fc2_w + (size_t)l * 4 * Dm * Dm, gpart, TD, Dm, 4 * Dm, 4 * Dm / 3);
        if (l + 1 < Ln) {
            redln_kernel<<<TD, 256>>>(gpart, fc2_b + (size_t)l * Dm, x, x,
                                      ln1_g + (l + 1) * Dm, ln1_b + (l + 1) * Dm, h, 1e-6f);
        } else {
            redln_kernel<<<TD, 256>>>(gpart, fc2_b + (size_t)l * Dm, x, x,
                                      lnf_g, lnf_b, h, 1e-5f);   // final LN
        }
    }

    transpose_wte<<<dim3(Vv / 32, Dm / 32), dim3(32, 8)>>>(wte, wteT);

    // LM head: [2048,768] @ wteT[768,50304]  grid 16x393 = 6288
    gemm_f32<<<dim3(TD / 128, Vv / 128), 256, GEMM_SMEM_128>>>(
        h, wteT, head_b, out, TD, Vv, Dm, 0);
}

// round 15
// speedup vs baseline: 1.0329x; 1.0006x over previous
#include <cuda_runtime.h>
#include <math.h>
#include <stdint.h>

#define Bsz 2
#define Ssz 1024
#define Dm  768
#define Hn  12
#define HDm 64
#define Ln  12
#define Vv  50304
#define TD  (Bsz*Ssz)   /* 2048 rows */
#define BK  32

typedef unsigned long long u64t;

// ================= helpers =================
__device__ __forceinline__ uint32_t smem_u32(const void* p) {
    uint32_t a;
    asm("{ .reg .u64 t; cvta.to.shared.u64 t, %1; cvt.u32.u64 %0, t; }" : "=r"(a) : "l"(p));
    return a;
}
#define CP_ASYNC16(s, g) asm volatile("cp.async.cg.shared.global [%0], [%1], 16;" :: "r"(s), "l"(g))
#define CP_COMMIT()      asm volatile("cp.async.commit_group;" ::: "memory")
#define CP_WAIT(n)       asm volatile("cp.async.wait_group %0;" :: "n"(n) : "memory")

__device__ __forceinline__ void ffma2(u64t& acc, u64t a, u64t b) {
    asm volatile("fma.rn.f32x2 %0, %1, %2, %0;" : "+l"(acc) : "l"(a), "l"(b));
}
__device__ __forceinline__ u64t splat2(float a) {
    u64t r; asm("mov.b64 %0, {%1, %1};" : "=l"(r) : "f"(a)); return r;
}
__device__ __forceinline__ u64t pack2(float lo, float hi) {
    u64t r; asm("mov.b64 %0, {%1, %2};" : "=l"(r) : "f"(lo), "f"(hi)); return r;
}
__device__ __forceinline__ float2 unpack2(u64t v) {
    float2 f; asm("mov.b64 {%0, %1}, %2;" : "=f"(f.x), "=f"(f.y) : "l"(v)); return f;
}

// ================= scratch =================
__device__ __align__(256) float g_x   [TD * Dm];
__device__ __align__(256) float g_h   [TD * Dm];
__device__ __align__(256) float g_qkv [TD * 3 * Dm];
__device__ __align__(256) float g_o   [TD * Dm];
__device__ __align__(256) float g_mlp [TD * 4 * Dm];
__device__ __align__(256) float g_madd[TD];
__device__ __align__(256) float g_wteT[(size_t)Dm * Vv];                // [768][50304]
__device__ __align__(256) float g_s   [(size_t)Bsz * Hn * Ssz * Ssz];  // scores/probs
__device__ __align__(256) float g_part [4][TD * Dm];                   // pv k-split partials
__device__ __align__(256) float g_gpart[3][TD * Dm];                   // proj/fc2 split-K partials

// ================= wte transpose (runs on side stream) =================
__global__ void transpose_wte(const float* __restrict__ w, float* __restrict__ wt) {
    __shared__ float t[32][33];
    int v0 = blockIdx.x * 32, d0 = blockIdx.y * 32;
#pragma unroll
    for (int i = 0; i < 4; i++)
        t[threadIdx.y + i * 8][threadIdx.x] =
            w[(size_t)(v0 + threadIdx.y + i * 8) * Dm + d0 + threadIdx.x];
    __syncthreads();
#pragma unroll
    for (int i = 0; i < 4; i++)
        wt[(size_t)(d0 + threadIdx.y + i * 8) * Vv + v0 + threadIdx.x] =
            t[threadIdx.x][threadIdx.y + i * 8];
}

// ================= mask =================
__global__ void maskprep_kernel(const float* __restrict__ amask, float* __restrict__ madd) {
    int i = blockIdx.x * blockDim.x + threadIdx.x;
    if (i < TD) madd[i] = (1.0f - amask[i]) * -10000.0f;
}

// ========= fused embed + ln0: x = wte[id]+wpe ; h = LN(x; g,b,eps) =========
__global__ void embedln_kernel(const int* __restrict__ ids, const float* __restrict__ wte,
                               const float* __restrict__ wpe, float* __restrict__ x,
                               const float* __restrict__ g, const float* __restrict__ b,
                               float* __restrict__ h, float eps) {
    int row = blockIdx.x, tid = threadIdx.x;
    int s = row % Ssz;
    size_t wbase = (size_t)ids[row] * Dm;
    size_t pbase = (size_t)s * Dm;
    size_t base = (size_t)row * Dm;
    float v[3];
#pragma unroll
    for (int j = 0; j < 3; j++) {
        int c = tid + j * 256;
        float t = wte[wbase + c] + wpe[pbase + c];
        x[base + c] = t;
        v[j] = t;
    }
    __shared__ float red[256];
    red[tid] = v[0] + v[1] + v[2];
    __syncthreads();
    for (int o = 128; o > 0; o >>= 1) { if (tid < o) red[tid] += red[tid + o]; __syncthreads(); }
    float mu = red[0] * (1.0f / Dm);
    __syncthreads();
    float d0 = v[0] - mu, d1 = v[1] - mu, d2 = v[2] - mu;
    red[tid] = d0 * d0 + d1 * d1 + d2 * d2;
    __syncthreads();
    for (int o = 128; o > 0; o >>= 1) { if (tid < o) red[tid] += red[tid + o]; __syncthreads(); }
    float rstd = rsqrtf(red[0] * (1.0f / Dm) + eps);
    float* hr = h + base;
    hr[tid]       = d0 * rstd * g[tid]       + b[tid];
    hr[tid + 256] = d1 * rstd * g[tid + 256] + b[tid + 256];
    hr[tid + 512] = d2 * rstd * g[tid + 512] + b[tid + 512];
}

// ========= fused: x = p0+p1+p2 + bias + res ;  h = LN(x; g,b,eps) =========
__global__ void redln_kernel(const float* __restrict__ Part, const float* __restrict__ bias,
                             const float* __restrict__ res, float* __restrict__ x,
                             const float* __restrict__ g, const float* __restrict__ b,
                             float* __restrict__ h, float eps) {
    int row = blockIdx.x, tid = threadIdx.x;
    size_t base = (size_t)row * Dm;
    float v[3];
#pragma unroll
    for (int j = 0; j < 3; j++) {
        int c = tid + j * 256;
        size_t idx = base + c;
        float s = ((Part[idx] + Part[(size_t)TD * Dm + idx]) + Part[2 * (size_t)TD * Dm + idx])
                  + bias[c] + res[idx];
        x[idx] = s;
        v[j] = s;
    }
    __shared__ float red[256];
    red[tid] = v[0] + v[1] + v[2];
    __syncthreads();
    for (int o = 128; o > 0; o >>= 1) { if (tid < o) red[tid] += red[tid + o]; __syncthreads(); }
    float mu = red[0] * (1.0f / Dm);
    __syncthreads();
    float d0 = v[0] - mu, d1 = v[1] - mu, d2 = v[2] - mu;
    red[tid] = d0 * d0 + d1 * d1 + d2 * d2;
    __syncthreads();
    for (int o = 128; o > 0; o >>= 1) { if (tid < o) red[tid] += red[tid + o]; __syncthreads(); }
    float rstd = rsqrtf(red[0] * (1.0f / Dm) + eps);
    float* hr = h + base;
    hr[tid]       = d0 * rstd * g[tid]       + b[tid];
    hr[tid + 256] = d1 * rstd * g[tid + 256] + b[tid + 256];
    hr[tid + 512] = d2 * rstd * g[tid + 512] + b[tid + 512];
}

// ================= attention: score GEMM S = Q K^T/8 (+mask) =================
// Only k <= q entries are ever read downstream; all other stores are skipped.
#define SPAD 68
#define SCORE_SMEM (2 * 128 * SPAD * 4)
__global__ void __launch_bounds__(256)
score_kernel(const float* __restrict__ qkv, const float* __restrict__ madd,
             float* __restrict__ S) {
    if (blockIdx.y > blockIdx.x) return;   // fully causal-masked tile
    int bh = blockIdx.z, b = bh / Hn, h = bh % Hn;
    int q0 = blockIdx.x * 128, k0 = blockIdx.y * 128;
    int tid = threadIdx.x, tx = tid & 15, ty = tid >> 4;

    extern __shared__ float sc_sm[];
    float* Qs = sc_sm;
    float* Ks = sc_sm + 128 * SPAD;
#pragma unroll
    for (int it = 0; it < 8; it++) {
        int idx = it * 256 + tid;
        int r = idx >> 4, c4 = idx & 15;
        float4 vq = *(const float4*)(qkv + (size_t)(b * Ssz + q0 + r) * (3 * Dm) + h * 3 * HDm + c4 * 4);
        *(float4*)(Qs + r * SPAD + c4 * 4) = vq;
        float4 vk = *(const float4*)(qkv + (size_t)(b * Ssz + k0 + r) * (3 * Dm) + h * 3 * HDm + HDm + c4 * 4);
        *(float4*)(Ks + r * SPAD + c4 * 4) = vk;
    }
    __syncthreads();

    u64t acc[8][4];
#pragma unroll
    for (int i = 0; i < 8; i++)
#pragma unroll
        for (int p = 0; p < 4; p++) acc[i][p] = 0ULL;

#pragma unroll 4
    for (int d = 0; d < HDm; d++) {
        float bv[8];
#pragma unroll
        for (int j = 0; j < 8; j++) bv[j] = Ks[(tx + 16 * j) * SPAD + d];
        u64t bp[4];
#pragma unroll
        for (int p = 0; p < 4; p++) bp[p] = pack2(bv[2 * p], bv[2 * p + 1]);
#pragma unroll
        for (int i = 0; i < 8; i++) {
            u64t aa = splat2(Qs[(ty * 8 + i) * SPAD + d]);
#pragma unroll
            for (int p = 0; p < 4; p++) ffma2(acc[i][p], aa, bp[p]);
        }
    }

    float ma[8];
#pragma unroll
    for (int j = 0; j < 8; j++) ma[j] = madd[b * Ssz + k0 + tx + 16 * j];
#pragma unroll
    for (int i = 0; i < 8; i++) {
        int q = q0 + ty * 8 + i;
        float* srow = S + ((size_t)bh * Ssz + q) * Ssz + k0;
#pragma unroll
        for (int p = 0; p < 4; p++) {
            float2 v = unpack2(acc[i][p]);
            int j0 = 2 * p, j1 = 2 * p + 1;
            int kg0 = k0 + tx + 16 * j0, kg1 = k0 + tx + 16 * j1;
            if (kg0 <= q) srow[tx + 16 * j0] = v.x * 0.125f + ma[j0];
            if (kg1 <= q) srow[tx + 16 * j1] = v.y * 0.125f + ma[j1];
        }
    }
}

// ================= attention: prefix softmax in place =================
__global__ void __launch_bounds__(256)
softmax_kernel(float* __restrict__ S) {
    size_t row = blockIdx.x;
    int q = (int)(row & (Ssz - 1));
    float* r = S + row * Ssz;
    int tid = threadIdx.x;
    int idx = tid * 4;
    __shared__ float red[256];

    float4 v = make_float4(0.f, 0.f, 0.f, 0.f);
    bool load = (idx <= q);
    float lmax = -1e30f;
    if (load) {
        v = *(float4*)(r + idx);
        lmax = v.x;
        if (idx + 1 <= q) lmax = fmaxf(lmax, v.y);
        if (idx + 2 <= q) lmax = fmaxf(lmax, v.z);
        if (idx + 3 <= q) lmax = fmaxf(lmax, v.w);
    }
    red[tid] = lmax;
    __syncthreads();
    for (int o = 128; o > 0; o >>= 1) { if (tid < o) red[tid] = fmaxf(red[tid], red[tid + o]); __syncthreads(); }
    float mx = red[0];
    __syncthreads();

    float e0 = 0.f, e1 = 0.f, e2 = 0.f, e3 = 0.f;
    if (load) {
        e0 = __expf(v.x - mx);
        e1 = (idx + 1 <= q) ? __expf(v.y - mx) : 0.f;
        e2 = (idx + 2 <= q) ? __expf(v.z - mx) : 0.f;
        e3 = (idx + 3 <= q) ? __expf(v.w - mx) : 0.f;
    }
    red[tid] = e0 + e1 + e2 + e3;
    __syncthreads();
    for (int o = 128; o > 0; o >>= 1) { if (tid < o) red[tid] += red[tid + o]; __syncthreads(); }
    float inv = 1.0f / red[0];

    int kend = ((q >> 8) + 1) << 8;
    if (idx < kend) {
        float4 w;
        w.x = (idx     <= q) ? e0 * inv : 0.f;
        w.y = (idx + 1 <= q) ? e1 * inv : 0.f;
        w.z = (idx + 2 <= q) ? e2 * inv : 0.f;
        w.w = (idx + 3 <= q) ? e3 * inv : 0.f;
        *(float4*)(r + idx) = w;
    }
}

// ================= attention: O_partial = P slab @ V slab =================
#define PPAD 36
#define PS_FLOATS (128 * PPAD)
#define VS_FLOATS (32 * 64)
#define PV_SMEM (2 * (PS_FLOATS + VS_FLOATS) * 4)
__global__ void __launch_bounds__(256)
pv_kernel(const float* __restrict__ P, const float* __restrict__ qkv,
          float* __restrict__ part) {
    int bh = blockIdx.y, b = bh / Hn, h = bh % Hn;
    int q0 = blockIdx.x * 128;
    int ks = blockIdx.z;
    int kbase = ks * 256;
    if (kbase > q0 + 127) return;
    int tid = threadIdx.x, tx = tid & 7, ty = tid >> 3;

    int span = q0 + 128 - kbase;
    const int NCK = (span >= 256) ? 8 : 4;

    extern __shared__ float pv_sm[];
    float* ps = pv_sm;
    float* vs = pv_sm + 2 * PS_FLOATS;
    const uint32_t sbP = smem_u32(pv_sm);
    const uint32_t sbV = sbP + 2 * PS_FLOATS * 4;

    const float* Pg = P + (size_t)bh * Ssz * Ssz;

    auto issueP = [&](int kc, int buf) {
        uint32_t base = sbP + buf * PS_FLOATS * 4;
#pragma unroll
        for (int it = 0; it < 4; it++) {
            int idx = it * 256 + tid;
            int r = idx >> 3, c4 = idx & 7;
            CP_ASYNC16(base + (uint32_t)(r * PPAD + c4 * 4) * 4,
                       Pg + (size_t)(q0 + r) * Ssz + kbase + kc * 32 + c4 * 4);
        }
    };
    auto issueV = [&](int kc, int buf) {
        uint32_t base = sbV + buf * VS_FLOATS * 4;
#pragma unroll
        for (int it = 0; it < 2; it++) {
            int idx = it * 256 + tid;
            int r = idx >> 4, c4 = idx & 15;
            CP_ASYNC16(base + (uint32_t)(r * 64 + c4 * 4) * 4,
                       qkv + (size_t)(b * Ssz + kbase + kc * 32 + r) * (3 * Dm) + h * 3 * HDm + 2 * HDm + c4 * 4);
        }
    };

    u64t acc[4][4];
#pragma unroll
    for (int i = 0; i < 4; i++)
#pragma unroll
        for (int j = 0; j < 4; j++) acc[i][j] = 0ULL;

    issueP(0, 0); issueV(0, 0); CP_COMMIT();
    for (int cc = 0; cc < NCK; cc++) {
        if (cc + 1 < NCK) {
            issueP(cc + 1, (cc + 1) & 1); issueV(cc + 1, (cc + 1) & 1); CP_COMMIT();
            CP_WAIT(1);
        } else {
            CP_WAIT(0);
        }
        __syncthreads();
        const float* Pb = ps + (cc & 1) * PS_FLOATS;
        const float* Vb = vs + (cc & 1) * VS_FLOATS;
#pragma unroll 4
        for (int k = 0; k < 32; k++) {
            const float* vrow = Vb + k * 64 + tx * 8;
            u64t b0 = *(const u64t*)(vrow);
            u64t b1 = *(const u64t*)(vrow + 2);
            u64t b2 = *(const u64t*)(vrow + 4);
            u64t b3 = *(const u64t*)(vrow + 6);
#pragma unroll
            for (int i = 0; i < 4; i++) {
                u64t aa = splat2(Pb[(ty * 4 + i) * PPAD + k]);
                ffma2(acc[i][0], aa, b0);
                ffma2(acc[i][1], aa, b1);
                ffma2(acc[i][2], aa, b2);
                ffma2(acc[i][3], aa, b3);
            }
        }
        __syncthreads();
    }

    float* op = part + (size_t)ks * TD * Dm;
#pragma unroll
    for (int i = 0; i < 4; i++) {
        int q = q0 + ty * 4 + i;
        float* orow = op + (size_t)(b * Ssz + q) * Dm + h * HDm + tx * 8;
        float2 p0 = unpack2(acc[i][0]), p1 = unpack2(acc[i][1]);
        float2 p2 = unpack2(acc[i][2]), p3 = unpack2(acc[i][3]);
        *(float4*)(orow)     = make_float4(p0.x, p0.y, p1.x, p1.y);
        *(float4*)(orow + 4) = make_float4(p2.x, p2.y, p3.x, p3.y);
    }
}

// ================= pv partial reduce =================
__global__ void pvreduce_kernel(const float* __restrict__ part, float* __restrict__ O) {
    int i = blockIdx.x * blockDim.x + threadIdx.x;
    if (i >= TD * Dm) return;
    int t = i / Dm;
    int q = t % Ssz;
    int q0 = q & ~127;
    int ns = (q0 + 127) / 256 + 1;
    float s = part[i];
    if (ns > 1) s += part[(size_t)TD * Dm + i];
    if (ns > 2) s += part[2 * (size_t)TD * Dm + i];
    if (ns > 3) s += part[3 * (size_t)TD * Dm + i];
    O[i] = s;
}

// ================= fp32 FFMA2 GEMM (NN), BK=32, CTA 128x128 =================
// epi 0: bias | 1: bias+gelu(exact)
#define GEMM_SMEM_128 (3 * (128 * 36 + 32 * 128) * 4)
__global__ void __launch_bounds__(256, 2)
gemm_f32(const float* __restrict__ A, const float* __restrict__ B,
         const float* __restrict__ bias, float* __restrict__ C,
         int M, int N, int K, int epi) {
    constexpr int ASZF = 128 * 36;
    constexpr int BSZF = 32 * 128;
    extern __shared__ float sm[];
    float* as_ = sm;
    float* bs_ = sm + 3 * ASZF;
    const uint32_t sbA = smem_u32(sm);
    const uint32_t sbB = sbA + 3 * ASZF * 4;
    const int tid = threadIdx.x;
    const int tx = tid & 15, ty = tid >> 4;
    const int m0 = blockIdx.x * 128;
    const int n0 = blockIdx.y * 128;

    u64t acc[8][4];
#pragma unroll
    for (int i = 0; i < 8; i++)
#pragma unroll
        for (int j = 0; j < 4; j++) acc[i][j] = 0ULL;

    const int NC = K / BK;
    const float* gA = A + (size_t)m0 * K;
    const float* gB = B + n0;

    auto issueA = [&](int kc, int buf) {
        uint32_t base = sbA + buf * ASZF * 4;
        int k0 = kc * BK;
#pragma unroll
        for (int p = 0; p < 4; p++) {
            int idx = p * 256 + tid;
            int r = idx >> 3, c4 = idx & 7;
            CP_ASYNC16(base + (uint32_t)(r * 36 + c4 * 4) * 4,
                       gA + (size_t)r * K + k0 + c4 * 4);
        }
    };
    auto issueB = [&](int kc, int buf) {
        uint32_t base = sbB + buf * BSZF * 4;
        int k0 = kc * BK;
#pragma unroll
        for (int p = 0; p < 4; p++) {
            int idx = p * 256 + tid;
            int r = idx >> 5, c4 = idx & 31;
            CP_ASYNC16(base + (uint32_t)(r * 128 + c4 * 4) * 4,
                       gB + (size_t)(k0 + r) * N + c4 * 4);
        }
    };

    auto compute = [&](int buf) {
        const float* Ab = as_ + buf * ASZF;
        const float* Bb = bs_ + buf * BSZF;
#pragma unroll 8
        for (int h = 0; h < 16; h++) {
            float2 a2[8];
#pragma unroll
            for (int i = 0; i < 8; i++)
                a2[i] = *(const float2*)(Ab + (ty * 8 + i) * 36 + h * 2);
#pragma unroll
            for (int k2 = 0; k2 < 2; k2++) {
                const float* brow = Bb + (h * 2 + k2) * 128 + tx * 8;
                u64t b0 = *(const u64t*)(brow);
                u64t b1 = *(const u64t*)(brow + 2);
                u64t b2 = *(const u64t*)(brow + 4);
                u64t b3 = *(const u64t*)(brow + 6);
#pragma unroll
                for (int i = 0; i < 8; i++) {
                    u64t aa = splat2(k2 ? a2[i].y : a2[i].x);
                    ffma2(acc[i][0], aa, b0);
                    ffma2(acc[i][1], aa, b1);
                    ffma2(acc[i][2], aa, b2);
                    ffma2(acc[i][3], aa, b3);
                }
            }
        }
    };

    issueA(0, 0); issueB(0, 0); CP_COMMIT();
    issueA(1, 1); issueB(1, 1); CP_COMMIT();
    for (int cc = 0; cc < NC; cc++) {
        if (cc + 1 < NC) { CP_WAIT(1); } else { CP_WAIT(0); }
        __syncthreads();
        if (cc + 2 < NC) {
            int nb = (cc + 2) % 3;
            issueA(cc + 2, nb); issueB(cc + 2, nb); CP_COMMIT();
        }
        compute(cc % 3);
    }

    const int ncol = n0 + tx * 8;
    float4 bb0 = *(const float4*)(bias + ncol);
    float4 bb1 = *(const float4*)(bias + ncol + 4);
#pragma unroll
    for (int i = 0; i < 8; i++) {
        int m = m0 + ty * 8 + i;
        size_t off = (size_t)m * N + ncol;
        float o[8];
        float2 p;
        p = unpack2(acc[i][0]); o[0] = p.x + bb0.x; o[1] = p.y + bb0.y;
        p = unpack2(acc[i][1]); o[2] = p.x + bb0.z; o[3] = p.y + bb0.w;
        p = unpack2(acc[i][2]); o[4] = p.x + bb1.x; o[5] = p.y + bb1.y;
        p = unpack2(acc[i][3]); o[6] = p.x + bb1.z; o[7] = p.y + bb1.w;
        if (epi == 1) {
#pragma unroll
            for (int j = 0; j < 8; j++) {
                float g = o[j];
                o[j] = 0.5f * g * (1.0f + erff(g * 0.70710678118654752f));
            }
        }
        *(float4*)(C + off)     = make_float4(o[0], o[1], o[2], o[3]);
        *(float4*)(C + off + 4) = make_float4(o[4], o[5], o[6], o[7]);
    }
}

// ================= split-K GEMM partial: raw slab output =================
__global__ void __launch_bounds__(256, 2)
gemm_pk(const float* __restrict__ A, const float* __restrict__ B,
        float* __restrict__ Part, int M, int N, int K, int KS) {
    constexpr int ASZF = 128 * 36;
    constexpr int BSZF = 32 * 128;
    extern __shared__ float sm[];
    float* as_ = sm;
    float* bs_ = sm + 3 * ASZF;
    const uint32_t sbA = smem_u32(sm);
    const uint32_t sbB = sbA + 3 * ASZF * 4;
    const int tid = threadIdx.x;
    const int tx = tid & 15, ty = tid >> 4;
    const int m0 = blockIdx.x * 128;
    const int n0 = blockIdx.y * 128;
    const int ks = blockIdx.z;
    const int kbeg = ks * KS;

    u64t acc[8][4];
#pragma unroll
    for (int i = 0; i < 8; i++)
#pragma unroll
        for (int j = 0; j < 4; j++) acc[i][j] = 0ULL;

    const int NC = KS / BK;
    const float* gA = A + (size_t)m0 * K + kbeg;
    const float* gB = B + (size_t)kbeg * N + n0;

    auto issueA = [&](int kc, int buf) {
        uint32_t base = sbA + buf * ASZF * 4;
        int k0 = kc * BK;
#pragma unroll
        for (int p = 0; p < 4; p++) {
            int idx = p * 256 + tid;
            int r = idx >> 3, c4 = idx & 7;
            CP_ASYNC16(base + (uint32_t)(r * 36 + c4 * 4) * 4,
                       gA + (size_t)r * K + k0 + c4 * 4);
        }
    };
    auto issueB = [&](int kc, int buf) {
        uint32_t base = sbB + buf * BSZF * 4;
        int k0 = kc * BK;
#pragma unroll
        for (int p = 0; p < 4; p++) {
            int idx = p * 256 + tid;
            int r = idx >> 5, c4 = idx & 31;
            CP_ASYNC16(base + (uint32_t)(r * 128 + c4 * 4) * 4,
                       gB + (size_t)(k0 + r) * N + c4 * 4);
        }
    };

    auto compute = [&](int buf) {
        const float* Ab = as_ + buf * ASZF;
        const float* Bb = bs_ + buf * BSZF;
#pragma unroll 8
        for (int h = 0; h < 16; h++) {
            float2 a2[8];
#pragma unroll
            for (int i = 0; i < 8; i++)
                a2[i] = *(const float2*)(Ab + (ty * 8 + i) * 36 + h * 2);
#pragma unroll
            for (int k2 = 0; k2 < 2; k2++) {
                const float* brow = Bb + (h * 2 + k2) * 128 + tx * 8;
                u64t b0 = *(const u64t*)(brow);
                u64t b1 = *(const u64t*)(brow + 2);
                u64t b2 = *(const u64t*)(brow + 4);
                u64t b3 = *(const u64t*)(brow + 6);
#pragma unroll
                for (int i = 0; i < 8; i++) {
                    u64t aa = splat2(k2 ? a2[i].y : a2[i].x);
                    ffma2(acc[i][0], aa, b0);
                    ffma2(acc[i][1], aa, b1);
                    ffma2(acc[i][2], aa, b2);
                    ffma2(acc[i][3], aa, b3);
                }
            }
        }
    };

    issueA(0, 0); issueB(0, 0); CP_COMMIT();
    issueA(1, 1); issueB(1, 1); CP_COMMIT();
    for (int cc = 0; cc < NC; cc++) {
        if (cc + 1 < NC) { CP_WAIT(1); } else { CP_WAIT(0); }
        __syncthreads();
        if (cc + 2 < NC) {
            int nb = (cc + 2) % 3;
            issueA(cc + 2, nb); issueB(cc + 2, nb); CP_COMMIT();
        }
        compute(cc % 3);
    }

    float* P = Part + (size_t)ks * TD * Dm;
    const int ncol = n0 + tx * 8;
#pragma unroll
    for (int i = 0; i < 8; i++) {
        int m = m0 + ty * 8 + i;
        size_t off = (size_t)m * N + ncol;
        float2 p0 = unpack2(acc[i][0]), p1 = unpack2(acc[i][1]);
        float2 p2 = unpack2(acc[i][2]), p3 = unpack2(acc[i][3]);
        *(float4*)(P + off)     = make_float4(p0.x, p0.y, p1.x, p1.y);
        *(float4*)(P + off + 4) = make_float4(p2.x, p2.y, p3.x, p3.y);
    }
}

// ================= host orchestration =================
extern "C" void kernel_launch(void* const* d_in, const int* in_sizes, int n_in,
                              void* d_out, int out_size) {
    const int*   ids    = (const int*)  d_in[0];
    const float* amask  = (const float*)d_in[1];
    const float* wte    = (const float*)d_in[2];
    const float* wpe    = (const float*)d_in[3];
    const float* ln1_g  = (const float*)d_in[4];
    const float* ln1_b  = (const float*)d_in[5];
    const float* qkv_w  = (const float*)d_in[6];
    const float* qkv_b  = (const float*)d_in[7];
    const float* proj_w = (const float*)d_in[8];
    const float* proj_b = (const float*)d_in[9];
    const float* ln2_g  = (const float*)d_in[10];
    const float* ln2_b  = (const float*)d_in[11];
    const float* fc1_w  = (const float*)d_in[12];
    const float* fc1_b  = (const float*)d_in[13];
    const float* fc2_w  = (const float*)d_in[14];
    const float* fc2_b  = (const float*)d_in[15];
    const float* lnf_g  = (const float*)d_in[16];
    const float* lnf_b  = (const float*)d_in[17];
    const float* head_b = (const float*)d_in[18];
    float* out = (float*)d_out;

    float *x, *h, *qkv, *o, *mlp, *madd, *wteT, *S, *part, *gpart;
    cudaGetSymbolAddress((void**)&x,     g_x);
    cudaGetSymbolAddress((void**)&h,     g_h);
    cudaGetSymbolAddress((void**)&qkv,   g_qkv);
    cudaGetSymbolAddress((void**)&o,     g_o);
    cudaGetSymbolAddress((void**)&mlp,   g_mlp);
    cudaGetSymbolAddress((void**)&madd,  g_madd);
    cudaGetSymbolAddress((void**)&wteT,  g_wteT);
    cudaGetSymbolAddress((void**)&S,     g_s);
    cudaGetSymbolAddress((void**)&part,  g_part);
    cudaGetSymbolAddress((void**)&gpart, g_gpart);

    cudaFuncSetAttribute(gemm_f32,     cudaFuncAttributeMaxDynamicSharedMemorySize, GEMM_SMEM_128);
    cudaFuncSetAttribute(gemm_pk,      cudaFuncAttributeMaxDynamicSharedMemorySize, GEMM_SMEM_128);
    cudaFuncSetAttribute(score_kernel, cudaFuncAttributeMaxDynamicSharedMemorySize, SCORE_SMEM);
    cudaFuncSetAttribute(pv_kernel,    cudaFuncAttributeMaxDynamicSharedMemorySize, PV_SMEM);

    // side stream + events (created once; resource creation only, work unchanged)
    static cudaStream_t s2 = nullptr;
    static cudaEvent_t evF = nullptr, evJ = nullptr;
    if (s2 == nullptr) {
        cudaStreamCreateWithFlags(&s2, cudaStreamNonBlocking);
        cudaEventCreateWithFlags(&evF, cudaEventDisableTiming);
        cudaEventCreateWithFlags(&evJ, cudaEventDisableTiming);
    }

    // fork: run wte transpose concurrently with the layer stack
    cudaEventRecord(evF, 0);
    cudaStreamWaitEvent(s2, evF, 0);
    transpose_wte<<<dim3(Vv / 32, Dm / 32), dim3(32, 8), 0, s2>>>(wte, wteT);
    cudaEventRecord(evJ, s2);

    maskprep_kernel<<<(TD + 255) / 256, 256>>>(amask, madd);
    // fused embed + ln1(layer 0) -> x, h
    embedln_kernel<<<TD, 256>>>(ids, wte, wpe, x, ln1_g, ln1_b, h, 1e-6f);

    for (int l = 0; l < Ln; l++) {
        // QKV: [2048,768] @ [768,2304]  grid 16x18 = 288
        gemm_f32<<<dim3(TD / 128, 3 * Dm / 128), 256, GEMM_SMEM_128>>>(
            h, qkv_w + (size_t)l * Dm * 3 * Dm, qkv_b + (size_t)l * 3 * Dm,
            qkv, TD, 3 * Dm, Dm, 0);
        // attention
        score_kernel<<<dim3(Ssz / 128, Ssz / 128, Bsz * Hn), 256, SCORE_SMEM>>>(qkv, madd, S);
        softmax_kernel<<<Bsz * Hn * Ssz, 256>>>(S);
        pv_kernel<<<dim3(Ssz / 128, Bsz * Hn, 4), 256, PV_SMEM>>>(S, qkv, part);
        pvreduce_kernel<<<(TD * Dm + 255) / 256, 256>>>(part, o);
        // proj: split-K=3, grid 16x6x3 = 288; fused reduce+bias+residual+LN2 -> x, h
        gemm_pk<<<dim3(TD / 128, Dm / 128, 3), 256, GEMM_SMEM_128>>>(
            o, proj_w + (size_t)l * Dm * Dm, gpart, TD, Dm, Dm, Dm / 3);
        redln_kernel<<<TD, 256>>>(gpart, proj_b + (size_t)l * Dm, x, x,
                                  ln2_g + l * Dm, ln2_b + l * Dm, h, 1e-6f);
        // fc1 + gelu: single pass, grid 16x24 = 384
        gemm_f32<<<dim3(TD / 128, 4 * Dm / 128), 256, GEMM_SMEM_128>>>(
            h, fc1_w + (size_t)l * Dm * 4 * Dm, fc1_b + (size_t)l * 4 * Dm,
            mlp, TD, 4 * Dm, Dm, 1);
        // fc2: split-K=3, grid 16x6x3 = 288; fused reduce+bias+residual+LN(next) -> x, h
        gemm_pk<<<dim3(TD / 128, Dm / 128, 3), 256, GEMM_SMEM_128>>>(
            mlp, fc2_w + (size_t)l * 4 * Dm * Dm, gpart, TD, Dm, 4 * Dm, 4 * Dm / 3);
        if (l + 1 < Ln) {
            redln_kernel<<<TD, 256>>>(gpart, fc2_b + (size_t)l * Dm, x, x,
                                      ln1_g + (l + 1) * Dm, ln1_b + (l + 1) * Dm, h, 1e-6f);
        } else {
            redln_kernel<<<TD, 256>>>(gpart, fc2_b + (size_t)l * Dm, x, x,
                                      lnf_g, lnf_b, h, 1e-5f);   // final LN
        }
    }

    // join: LM head needs wteT
    cudaStreamWaitEvent(0, evJ, 0);

    // LM head: [2048,768] @ wteT[768,50304]  grid 16x393 = 6288
    gemm_f32<<<dim3(TD / 128, Vv / 128), 256, GEMM_SMEM_128>>>(
        h, wteT, head_b, out, TD, Vv, Dm, 0);
}

// round 16
// speedup vs baseline: 1.0446x; 1.0113x over previous
#include <cuda_runtime.h>
#include <math.h>
#include <stdint.h>

#define Bsz 2
#define Ssz 1024
#define Dm  768
#define Hn  12
#define HDm 64
#define Ln  12
#define Vv  50304
#define TD  (Bsz*Ssz)   /* 2048 rows */
#define BK  32

typedef unsigned long long u64t;

// ================= helpers =================
__device__ __forceinline__ uint32_t smem_u32(const void* p) {
    uint32_t a;
    asm("{ .reg .u64 t; cvta.to.shared.u64 t, %1; cvt.u32.u64 %0, t; }" : "=r"(a) : "l"(p));
    return a;
}
#define CP_ASYNC16(s, g) asm volatile("cp.async.cg.shared.global [%0], [%1], 16;" :: "r"(s), "l"(g))
#define CP_COMMIT()      asm volatile("cp.async.commit_group;" ::: "memory")
#define CP_WAIT(n)       asm volatile("cp.async.wait_group %0;" :: "n"(n) : "memory")

__device__ __forceinline__ void ffma2(u64t& acc, u64t a, u64t b) {
    asm volatile("fma.rn.f32x2 %0, %1, %2, %0;" : "+l"(acc) : "l"(a), "l"(b));
}
__device__ __forceinline__ u64t splat2(float a) {
    u64t r; asm("mov.b64 %0, {%1, %1};" : "=l"(r) : "f"(a)); return r;
}
__device__ __forceinline__ u64t pack2(float lo, float hi) {
    u64t r; asm("mov.b64 %0, {%1, %2};" : "=l"(r) : "f"(lo), "f"(hi)); return r;
}
__device__ __forceinline__ float2 unpack2(u64t v) {
    float2 f; asm("mov.b64 {%0, %1}, %2;" : "=f"(f.x), "=f"(f.y) : "l"(v)); return f;
}

// ================= scratch =================
__device__ __align__(256) float g_x   [TD * Dm];
__device__ __align__(256) float g_h   [TD * Dm];
__device__ __align__(256) float g_qkv [TD * 3 * Dm];
__device__ __align__(256) float g_o   [TD * Dm];
__device__ __align__(256) float g_mlp [TD * 4 * Dm];
__device__ __align__(256) float g_madd[TD];
__device__ __align__(256) float g_wteT[(size_t)Dm * Vv];                // [768][50304]
__device__ __align__(256) float g_s   [(size_t)Bsz * Hn * Ssz * Ssz];  // scores/probs
__device__ __align__(256) float g_part [4][TD * Dm];                   // pv k-split partials
__device__ __align__(256) float g_gpart[3][TD * Dm];                   // proj/fc2 split-K partials

// ================= wte transpose (side stream) =================
__global__ void transpose_wte(const float* __restrict__ w, float* __restrict__ wt) {
    __shared__ float t[32][33];
    int v0 = blockIdx.x * 32, d0 = blockIdx.y * 32;
#pragma unroll
    for (int i = 0; i < 4; i++)
        t[threadIdx.y + i * 8][threadIdx.x] =
            w[(size_t)(v0 + threadIdx.y + i * 8) * Dm + d0 + threadIdx.x];
    __syncthreads();
#pragma unroll
    for (int i = 0; i < 4; i++)
        wt[(size_t)(d0 + threadIdx.y + i * 8) * Vv + v0 + threadIdx.x] =
            t[threadIdx.x][threadIdx.y + i * 8];
}

// ================= mask =================
__global__ void maskprep_kernel(const float* __restrict__ amask, float* __restrict__ madd) {
    int i = blockIdx.x * blockDim.x + threadIdx.x;
    if (i < TD) madd[i] = (1.0f - amask[i]) * -10000.0f;
}

// ========= fused embed + ln0 =========
__global__ void embedln_kernel(const int* __restrict__ ids, const float* __restrict__ wte,
                               const float* __restrict__ wpe, float* __restrict__ x,
                               const float* __restrict__ g, const float* __restrict__ b,
                               float* __restrict__ h, float eps) {
    int row = blockIdx.x, tid = threadIdx.x;
    int s = row % Ssz;
    size_t wbase = (size_t)ids[row] * Dm;
    size_t pbase = (size_t)s * Dm;
    size_t base = (size_t)row * Dm;
    float v[3];
#pragma unroll
    for (int j = 0; j < 3; j++) {
        int c = tid + j * 256;
        float t = wte[wbase + c] + wpe[pbase + c];
        x[base + c] = t;
        v[j] = t;
    }
    __shared__ float red[256];
    red[tid] = v[0] + v[1] + v[2];
    __syncthreads();
    for (int o = 128; o > 0; o >>= 1) { if (tid < o) red[tid] += red[tid + o]; __syncthreads(); }
    float mu = red[0] * (1.0f / Dm);
    __syncthreads();
    float d0 = v[0] - mu, d1 = v[1] - mu, d2 = v[2] - mu;
    red[tid] = d0 * d0 + d1 * d1 + d2 * d2;
    __syncthreads();
    for (int o = 128; o > 0; o >>= 1) { if (tid < o) red[tid] += red[tid + o]; __syncthreads(); }
    float rstd = rsqrtf(red[0] * (1.0f / Dm) + eps);
    float* hr = h + base;
    hr[tid]       = d0 * rstd * g[tid]       + b[tid];
    hr[tid + 256] = d1 * rstd * g[tid + 256] + b[tid + 256];
    hr[tid + 512] = d2 * rstd * g[tid + 512] + b[tid + 512];
}

// ========= fused: x = p0+p1+p2 + bias + res ;  h = LN(x) =========
__global__ void redln_kernel(const float* __restrict__ Part, const float* __restrict__ bias,
                             const float* __restrict__ res, float* __restrict__ x,
                             const float* __restrict__ g, const float* __restrict__ b,
                             float* __restrict__ h, float eps) {
    int row = blockIdx.x, tid = threadIdx.x;
    size_t base = (size_t)row * Dm;
    float v[3];
#pragma unroll
    for (int j = 0; j < 3; j++) {
        int c = tid + j * 256;
        size_t idx = base + c;
        float s = ((Part[idx] + Part[(size_t)TD * Dm + idx]) + Part[2 * (size_t)TD * Dm + idx])
                  + bias[c] + res[idx];
        x[idx] = s;
        v[j] = s;
    }
    __shared__ float red[256];
    red[tid] = v[0] + v[1] + v[2];
    __syncthreads();
    for (int o = 128; o > 0; o >>= 1) { if (tid < o) red[tid] += red[tid + o]; __syncthreads(); }
    float mu = red[0] * (1.0f / Dm);
    __syncthreads();
    float d0 = v[0] - mu, d1 = v[1] - mu, d2 = v[2] - mu;
    red[tid] = d0 * d0 + d1 * d1 + d2 * d2;
    __syncthreads();
    for (int o = 128; o > 0; o >>= 1) { if (tid < o) red[tid] += red[tid + o]; __syncthreads(); }
    float rstd = rsqrtf(red[0] * (1.0f / Dm) + eps);
    float* hr = h + base;
    hr[tid]       = d0 * rstd * g[tid]       + b[tid];
    hr[tid + 256] = d1 * rstd * g[tid + 256] + b[tid + 256];
    hr[tid + 512] = d2 * rstd * g[tid + 512] + b[tid + 512];
}

// ================= attention: score GEMM =================
#define SPAD 68
#define SCORE_SMEM (2 * 128 * SPAD * 4)
__global__ void __launch_bounds__(256)
score_kernel(const float* __restrict__ qkv, const float* __restrict__ madd,
             float* __restrict__ S) {
    if (blockIdx.y > blockIdx.x) return;
    int bh = blockIdx.z, b = bh / Hn, h = bh % Hn;
    int q0 = blockIdx.x * 128, k0 = blockIdx.y * 128;
    int tid = threadIdx.x, tx = tid & 15, ty = tid >> 4;

    extern __shared__ float sc_sm[];
    float* Qs = sc_sm;
    float* Ks = sc_sm + 128 * SPAD;
#pragma unroll
    for (int it = 0; it < 8; it++) {
        int idx = it * 256 + tid;
        int r = idx >> 4, c4 = idx & 15;
        float4 vq = *(const float4*)(qkv + (size_t)(b * Ssz + q0 + r) * (3 * Dm) + h * 3 * HDm + c4 * 4);
        *(float4*)(Qs + r * SPAD + c4 * 4) = vq;
        float4 vk = *(const float4*)(qkv + (size_t)(b * Ssz + k0 + r) * (3 * Dm) + h * 3 * HDm + HDm + c4 * 4);
        *(float4*)(Ks + r * SPAD + c4 * 4) = vk;
    }
    __syncthreads();

    u64t acc[8][4];
#pragma unroll
    for (int i = 0; i < 8; i++)
#pragma unroll
        for (int p = 0; p < 4; p++) acc[i][p] = 0ULL;

#pragma unroll 4
    for (int d = 0; d < HDm; d++) {
        float bv[8];
#pragma unroll
        for (int j = 0; j < 8; j++) bv[j] = Ks[(tx + 16 * j) * SPAD + d];
        u64t bp[4];
#pragma unroll
        for (int p = 0; p < 4; p++) bp[p] = pack2(bv[2 * p], bv[2 * p + 1]);
#pragma unroll
        for (int i = 0; i < 8; i++) {
            u64t aa = splat2(Qs[(ty * 8 + i) * SPAD + d]);
#pragma unroll
            for (int p = 0; p < 4; p++) ffma2(acc[i][p], aa, bp[p]);
        }
    }

    float ma[8];
#pragma unroll
    for (int j = 0; j < 8; j++) ma[j] = madd[b * Ssz + k0 + tx + 16 * j];
#pragma unroll
    for (int i = 0; i < 8; i++) {
        int q = q0 + ty * 8 + i;
        float* srow = S + ((size_t)bh * Ssz + q) * Ssz + k0;
#pragma unroll
        for (int p = 0; p < 4; p++) {
            float2 v = unpack2(acc[i][p]);
            int j0 = 2 * p, j1 = 2 * p + 1;
            int kg0 = k0 + tx + 16 * j0, kg1 = k0 + tx + 16 * j1;
            if (kg0 <= q) srow[tx + 16 * j0] = v.x * 0.125f + ma[j0];
            if (kg1 <= q) srow[tx + 16 * j1] = v.y * 0.125f + ma[j1];
        }
    }
}

// ================= attention: prefix softmax =================
__global__ void __launch_bounds__(256)
softmax_kernel(float* __restrict__ S) {
    size_t row = blockIdx.x;
    int q = (int)(row & (Ssz - 1));
    float* r = S + row * Ssz;
    int tid = threadIdx.x;
    int idx = tid * 4;
    __shared__ float red[256];

    float4 v = make_float4(0.f, 0.f, 0.f, 0.f);
    bool load = (idx <= q);
    float lmax = -1e30f;
    if (load) {
        v = *(float4*)(r + idx);
        lmax = v.x;
        if (idx + 1 <= q) lmax = fmaxf(lmax, v.y);
        if (idx + 2 <= q) lmax = fmaxf(lmax, v.z);
        if (idx + 3 <= q) lmax = fmaxf(lmax, v.w);
    }
    red[tid] = lmax;
    __syncthreads();
    for (int o = 128; o > 0; o >>= 1) { if (tid < o) red[tid] = fmaxf(red[tid], red[tid + o]); __syncthreads(); }
    float mx = red[0];
    __syncthreads();

    float e0 = 0.f, e1 = 0.f, e2 = 0.f, e3 = 0.f;
    if (load) {
        e0 = __expf(v.x - mx);
        e1 = (idx + 1 <= q) ? __expf(v.y - mx) : 0.f;
        e2 = (idx + 2 <= q) ? __expf(v.z - mx) : 0.f;
        e3 = (idx + 3 <= q) ? __expf(v.w - mx) : 0.f;
    }
    red[tid] = e0 + e1 + e2 + e3;
    __syncthreads();
    for (int o = 128; o > 0; o >>= 1) { if (tid < o) red[tid] += red[tid + o]; __syncthreads(); }
    float inv = 1.0f / red[0];

    int kend = ((q >> 8) + 1) << 8;
    if (idx < kend) {
        float4 w;
        w.x = (idx     <= q) ? e0 * inv : 0.f;
        w.y = (idx + 1 <= q) ? e1 * inv : 0.f;
        w.z = (idx + 2 <= q) ? e2 * inv : 0.f;
        w.w = (idx + 3 <= q) ? e3 * inv : 0.f;
        *(float4*)(r + idx) = w;
    }
}

// ================= attention: O_partial = P slab @ V slab =================
#define PPAD 36
#define PS_FLOATS (128 * PPAD)
#define VS_FLOATS (32 * 64)
#define PV_SMEM (2 * (PS_FLOATS + VS_FLOATS) * 4)
__global__ void __launch_bounds__(256)
pv_kernel(const float* __restrict__ P, const float* __restrict__ qkv,
          float* __restrict__ part) {
    int bh = blockIdx.y, b = bh / Hn, h = bh % Hn;
    int q0 = blockIdx.x * 128;
    int ks = blockIdx.z;
    int kbase = ks * 256;
    if (kbase > q0 + 127) return;
    int tid = threadIdx.x, tx = tid & 7, ty = tid >> 3;

    int span = q0 + 128 - kbase;
    const int NCK = (span >= 256) ? 8 : 4;

    extern __shared__ float pv_sm[];
    float* ps = pv_sm;
    float* vs = pv_sm + 2 * PS_FLOATS;
    const uint32_t sbP = smem_u32(pv_sm);
    const uint32_t sbV = sbP + 2 * PS_FLOATS * 4;

    const float* Pg = P + (size_t)bh * Ssz * Ssz;

    auto issueP = [&](int kc, int buf) {
        uint32_t base = sbP + buf * PS_FLOATS * 4;
#pragma unroll
        for (int it = 0; it < 4; it++) {
            int idx = it * 256 + tid;
            int r = idx >> 3, c4 = idx & 7;
            CP_ASYNC16(base + (uint32_t)(r * PPAD + c4 * 4) * 4,
                       Pg + (size_t)(q0 + r) * Ssz + kbase + kc * 32 + c4 * 4);
        }
    };
    auto issueV = [&](int kc, int buf) {
        uint32_t base = sbV + buf * VS_FLOATS * 4;
#pragma unroll
        for (int it = 0; it < 2; it++) {
            int idx = it * 256 + tid;
            int r = idx >> 4, c4 = idx & 15;
            CP_ASYNC16(base + (uint32_t)(r * 64 + c4 * 4) * 4,
                       qkv + (size_t)(b * Ssz + kbase + kc * 32 + r) * (3 * Dm) + h * 3 * HDm + 2 * HDm + c4 * 4);
        }
    };

    u64t acc[4][4];
#pragma unroll
    for (int i = 0; i < 4; i++)
#pragma unroll
        for (int j = 0; j < 4; j++) acc[i][j] = 0ULL;

    issueP(0, 0); issueV(0, 0); CP_COMMIT();
    for (int cc = 0; cc < NCK; cc++) {
        if (cc + 1 < NCK) {
            issueP(cc + 1, (cc + 1) & 1); issueV(cc + 1, (cc + 1) & 1); CP_COMMIT();
            CP_WAIT(1);
        } else {
            CP_WAIT(0);
        }
        __syncthreads();
        const float* Pb = ps + (cc & 1) * PS_FLOATS;
        const float* Vb = vs + (cc & 1) * VS_FLOATS;
#pragma unroll 4
        for (int k = 0; k < 32; k++) {
            const float* vrow = Vb + k * 64 + tx * 8;
            ulonglong2 bv0 = *(const ulonglong2*)(vrow);
            ulonglong2 bv1 = *(const ulonglong2*)(vrow + 4);
#pragma unroll
            for (int i = 0; i < 4; i++) {
                u64t aa = splat2(Pb[(ty * 4 + i) * PPAD + k]);
                ffma2(acc[i][0], aa, bv0.x);
                ffma2(acc[i][1], aa, bv0.y);
                ffma2(acc[i][2], aa, bv1.x);
                ffma2(acc[i][3], aa, bv1.y);
            }
        }
        __syncthreads();
    }

    float* op = part + (size_t)ks * TD * Dm;
#pragma unroll
    for (int i = 0; i < 4; i++) {
        int q = q0 + ty * 4 + i;
        float* orow = op + (size_t)(b * Ssz + q) * Dm + h * HDm + tx * 8;
        float2 p0 = unpack2(acc[i][0]), p1 = unpack2(acc[i][1]);
        float2 p2 = unpack2(acc[i][2]), p3 = unpack2(acc[i][3]);
        *(float4*)(orow)     = make_float4(p0.x, p0.y, p1.x, p1.y);
        *(float4*)(orow + 4) = make_float4(p2.x, p2.y, p3.x, p3.y);
    }
}

// ================= pv partial reduce =================
__global__ void pvreduce_kernel(const float* __restrict__ part, float* __restrict__ O) {
    int i = blockIdx.x * blockDim.x + threadIdx.x;
    if (i >= TD * Dm) return;
    int t = i / Dm;
    int q = t % Ssz;
    int q0 = q & ~127;
    int ns = (q0 + 127) / 256 + 1;
    float s = part[i];
    if (ns > 1) s += part[(size_t)TD * Dm + i];
    if (ns > 2) s += part[2 * (size_t)TD * Dm + i];
    if (ns > 3) s += part[3 * (size_t)TD * Dm + i];
    O[i] = s;
}

// ======== shared GEMM inner loop: 128-bit smem loads, k-order unchanged ========
// Per 4-k group: A one float4/row, B two ulonglong2/row. Bit-identical FFMA order.
#define GEMM_COMPUTE(Ab, Bb, acc)                                              \
    _Pragma("unroll")                                                          \
    for (int g_ = 0; g_ < 8; g_++) {                                           \
        float4 a4[8];                                                          \
        _Pragma("unroll")                                                      \
        for (int i = 0; i < 8; i++)                                            \
            a4[i] = *(const float4*)((Ab) + (ty * 8 + i) * 36 + g_ * 4);       \
        _Pragma("unroll")                                                      \
        for (int half_ = 0; half_ < 2; half_++) {                              \
            _Pragma("unroll")                                                  \
            for (int k2 = 0; k2 < 2; k2++) {                                   \
                const float* brow = (Bb) + (g_ * 4 + half_ * 2 + k2) * 128 + tx * 8; \
                ulonglong2 bv0 = *(const ulonglong2*)(brow);                   \
                ulonglong2 bv1 = *(const ulonglong2*)(brow + 4);               \
                _Pragma("unroll")                                              \
                for (int i = 0; i < 8; i++) {                                  \
                    float av = half_ ? (k2 ? a4[i].w : a4[i].z)                \
                                     : (k2 ? a4[i].y : a4[i].x);               \
                    u64t aa = splat2(av);                                      \
                    ffma2((acc)[i][0], aa, bv0.x);                             \
                    ffma2((acc)[i][1], aa, bv0.y);                             \
                    ffma2((acc)[i][2], aa, bv1.x);                             \
                    ffma2((acc)[i][3], aa, bv1.y);                             \
                }                                                              \
            }                                                                  \
        }                                                                      \
    }

// ================= fp32 FFMA2 GEMM (NN), BK=32, CTA 128x128 =================
#define GEMM_SMEM_128 (3 * (128 * 36 + 32 * 128) * 4)
__global__ void __launch_bounds__(256, 2)
gemm_f32(const float* __restrict__ A, const float* __restrict__ B,
         const float* __restrict__ bias, float* __restrict__ C,
         int M, int N, int K, int epi) {
    constexpr int ASZF = 128 * 36;
    constexpr int BSZF = 32 * 128;
    extern __shared__ float sm[];
    float* as_ = sm;
    float* bs_ = sm + 3 * ASZF;
    const uint32_t sbA = smem_u32(sm);
    const uint32_t sbB = sbA + 3 * ASZF * 4;
    const int tid = threadIdx.x;
    const int tx = tid & 15, ty = tid >> 4;
    const int m0 = blockIdx.x * 128;
    const int n0 = blockIdx.y * 128;

    u64t acc[8][4];
#pragma unroll
    for (int i = 0; i < 8; i++)
#pragma unroll
        for (int j = 0; j < 4; j++) acc[i][j] = 0ULL;

    const int NC = K / BK;
    const float* gA = A + (size_t)m0 * K;
    const float* gB = B + n0;

    auto issueA = [&](int kc, int buf) {
        uint32_t base = sbA + buf * ASZF * 4;
        int k0 = kc * BK;
#pragma unroll
        for (int p = 0; p < 4; p++) {
            int idx = p * 256 + tid;
            int r = idx >> 3, c4 = idx & 7;
            CP_ASYNC16(base + (uint32_t)(r * 36 + c4 * 4) * 4,
                       gA + (size_t)r * K + k0 + c4 * 4);
        }
    };
    auto issueB = [&](int kc, int buf) {
        uint32_t base = sbB + buf * BSZF * 4;
        int k0 = kc * BK;
#pragma unroll
        for (int p = 0; p < 4; p++) {
            int idx = p * 256 + tid;
            int r = idx >> 5, c4 = idx & 31;
            CP_ASYNC16(base + (uint32_t)(r * 128 + c4 * 4) * 4,
                       gB + (size_t)(k0 + r) * N + c4 * 4);
        }
    };

    issueA(0, 0); issueB(0, 0); CP_COMMIT();
    issueA(1, 1); issueB(1, 1); CP_COMMIT();
    for (int cc = 0; cc < NC; cc++) {
        if (cc + 1 < NC) { CP_WAIT(1); } else { CP_WAIT(0); }
        __syncthreads();
        if (cc + 2 < NC) {
            int nb = (cc + 2) % 3;
            issueA(cc + 2, nb); issueB(cc + 2, nb); CP_COMMIT();
        }
        const float* Ab = as_ + (cc % 3) * ASZF;
        const float* Bb = bs_ + (cc % 3) * BSZF;
        GEMM_COMPUTE(Ab, Bb, acc);
    }

    const int ncol = n0 + tx * 8;
    float4 bb0 = *(const float4*)(bias + ncol);
    float4 bb1 = *(const float4*)(bias + ncol + 4);
#pragma unroll
    for (int i = 0; i < 8; i++) {
        int m = m0 + ty * 8 + i;
        size_t off = (size_t)m * N + ncol;
        float o[8];
        float2 p;
        p = unpack2(acc[i][0]); o[0] = p.x + bb0.x; o[1] = p.y + bb0.y;
        p = unpack2(acc[i][1]); o[2] = p.x + bb0.z; o[3] = p.y + bb0.w;
        p = unpack2(acc[i][2]); o[4] = p.x + bb1.x; o[5] = p.y + bb1.y;
        p = unpack2(acc[i][3]); o[6] = p.x + bb1.z; o[7] = p.y + bb1.w;
        if (epi == 1) {
#pragma unroll
            for (int j = 0; j < 8; j++) {
                float g = o[j];
                o[j] = 0.5f * g * (1.0f + erff(g * 0.70710678118654752f));
            }
        }
        *(float4*)(C + off)     = make_float4(o[0], o[1], o[2], o[3]);
        *(float4*)(C + off + 4) = make_float4(o[4], o[5], o[6], o[7]);
    }
}

// ================= split-K GEMM partial =================
__global__ void __launch_bounds__(256, 2)
gemm_pk(const float* __restrict__ A, const float* __restrict__ B,
        float* __restrict__ Part, int M, int N, int K, int KS) {
    constexpr int ASZF = 128 * 36;
    constexpr int BSZF = 32 * 128;
    extern __shared__ float sm[];
    float* as_ = sm;
    float* bs_ = sm + 3 * ASZF;
    const uint32_t sbA = smem_u32(sm);
    const uint32_t sbB = sbA + 3 * ASZF * 4;
    const int tid = threadIdx.x;
    const int tx = tid & 15, ty = tid >> 4;
    const int m0 = blockIdx.x * 128;
    const int n0 = blockIdx.y * 128;
    const int ks = blockIdx.z;
    const int kbeg = ks * KS;

    u64t acc[8][4];
#pragma unroll
    for (int i = 0; i < 8; i++)
#pragma unroll
        for (int j = 0; j < 4; j++) acc[i][j] = 0ULL;

    const int NC = KS / BK;
    const float* gA = A + (size_t)m0 * K + kbeg;
    const float* gB = B + (size_t)kbeg * N + n0;

    auto issueA = [&](int kc, int buf) {
        uint32_t base = sbA + buf * ASZF * 4;
        int k0 = kc * BK;
#pragma unroll
        for (int p = 0; p < 4; p++) {
            int idx = p * 256 + tid;
            int r = idx >> 3, c4 = idx & 7;
            CP_ASYNC16(base + (uint32_t)(r * 36 + c4 * 4) * 4,
                       gA + (size_t)r * K + k0 + c4 * 4);
        }
    };
    auto issueB = [&](int kc, int buf) {
        uint32_t base = sbB + buf * BSZF * 4;
        int k0 = kc * BK;
#pragma unroll
        for (int p = 0; p < 4; p++) {
            int idx = p * 256 + tid;
            int r = idx >> 5, c4 = idx & 31;
            CP_ASYNC16(base + (uint32_t)(r * 128 + c4 * 4) * 4,
                       gB + (size_t)(k0 + r) * N + c4 * 4);
        }
    };

    issueA(0, 0); issueB(0, 0); CP_COMMIT();
    issueA(1, 1); issueB(1, 1); CP_COMMIT();
    for (int cc = 0; cc < NC; cc++) {
        if (cc + 1 < NC) { CP_WAIT(1); } else { CP_WAIT(0); }
        __syncthreads();
        if (cc + 2 < NC) {
            int nb = (cc + 2) % 3;
            issueA(cc + 2, nb); issueB(cc + 2, nb); CP_COMMIT();
        }
        const float* Ab = as_ + (cc % 3) * ASZF;
        const float* Bb = bs_ + (cc % 3) * BSZF;
        GEMM_COMPUTE(Ab, Bb, acc);
    }

    float* P = Part + (size_t)ks * TD * Dm;
    const int ncol = n0 + tx * 8;
#pragma unroll
    for (int i = 0; i < 8; i++) {
        int m = m0 + ty * 8 + i;
        size_t off = (size_t)m * N + ncol;
        float2 p0 = unpack2(acc[i][0]), p1 = unpack2(acc[i][1]);
        float2 p2 = unpack2(acc[i][2]), p3 = unpack2(acc[i][3]);
        *(float4*)(P + off)     = make_float4(p0.x, p0.y, p1.x, p1.y);
        *(float4*)(P + off + 4) = make_float4(p2.x, p2.y, p3.x, p3.y);
    }
}

// ================= host orchestration =================
extern "C" void kernel_launch(void* const* d_in, const int* in_sizes, int n_in,
                              void* d_out, int out_size) {
    const int*   ids    = (const int*)  d_in[0];
    const float* amask  = (const float*)d_in[1];
    const float* wte    = (const float*)d_in[2];
    const float* wpe    = (const float*)d_in[3];
    const float* ln1_g  = (const float*)d_in[4];
    const float* ln1_b  = (const float*)d_in[5];
    const float* qkv_w  = (const float*)d_in[6];
    const float* qkv_b  = (const float*)d_in[7];
    const float* proj_w = (const float*)d_in[8];
    const float* proj_b = (const float*)d_in[9];
    const float* ln2_g  = (const float*)d_in[10];
    const float* ln2_b  = (const float*)d_in[11];
    const float* fc1_w  = (const float*)d_in[12];
    const float* fc1_b  = (const float*)d_in[13];
    const float* fc2_w  = (const float*)d_in[14];
    const float* fc2_b  = (const float*)d_in[15];
    const float* lnf_g  = (const float*)d_in[16];
    const float* lnf_b  = (const float*)d_in[17];
    const float* head_b = (const float*)d_in[18];
    float* out = (float*)d_out;

    float *x, *h, *qkv, *o, *mlp, *madd, *wteT, *S, *part, *gpart;
    cudaGetSymbolAddress((void**)&x,     g_x);
    cudaGetSymbolAddress((void**)&h,     g_h);
    cudaGetSymbolAddress((void**)&qkv,   g_qkv);
    cudaGetSymbolAddress((void**)&o,     g_o);
    cudaGetSymbolAddress((void**)&mlp,   g_mlp);
    cudaGetSymbolAddress((void**)&madd,  g_madd);
    cudaGetSymbolAddress((void**)&wteT,  g_wteT);
    cudaGetSymbolAddress((void**)&S,     g_s);
    cudaGetSymbolAddress((void**)&part,  g_part);
    cudaGetSymbolAddress((void**)&gpart, g_gpart);

    cudaFuncSetAttribute(gemm_f32,     cudaFuncAttributeMaxDynamicSharedMemorySize, GEMM_SMEM_128);
    cudaFuncSetAttribute(gemm_pk,      cudaFuncAttributeMaxDynamicSharedMemorySize, GEMM_SMEM_128);
    cudaFuncSetAttribute(score_kernel, cudaFuncAttributeMaxDynamicSharedMemorySize, SCORE_SMEM);
    cudaFuncSetAttribute(pv_kernel,    cudaFuncAttributeMaxDynamicSharedMemorySize, PV_SMEM);

    static cudaStream_t s2 = nullptr;
    static cudaEvent_t evF = nullptr, evJ = nullptr;
    if (s2 == nullptr) {
        cudaStreamCreateWithFlags(&s2, cudaStreamNonBlocking);
        cudaEventCreateWithFlags(&evF, cudaEventDisableTiming);
        cudaEventCreateWithFlags(&evJ, cudaEventDisableTiming);
    }

    // fork: wte transpose concurrent with layer stack
    cudaEventRecord(evF, 0);
    cudaStreamWaitEvent(s2, evF, 0);
    transpose_wte<<<dim3(Vv / 32, Dm / 32), dim3(32, 8), 0, s2>>>(wte, wteT);
    cudaEventRecord(evJ, s2);

    maskprep_kernel<<<(TD + 255) / 256, 256>>>(amask, madd);
    embedln_kernel<<<TD, 256>>>(ids, wte, wpe, x, ln1_g, ln1_b, h, 1e-6f);

    for (int l = 0; l < Ln; l++) {
        gemm_f32<<<dim3(TD / 128, 3 * Dm / 128), 256, GEMM_SMEM_128>>>(
            h, qkv_w + (size_t)l * Dm * 3 * Dm, qkv_b + (size_t)l * 3 * Dm,
            qkv, TD, 3 * Dm, Dm, 0);
        score_kernel<<<dim3(Ssz / 128, Ssz / 128, Bsz * Hn), 256, SCORE_SMEM>>>(qkv, madd, S);
        softmax_kernel<<<Bsz * Hn * Ssz, 256>>>(S);
        pv_kernel<<<dim3(Ssz / 128, Bsz * Hn, 4), 256, PV_SMEM>>>(S, qkv, part);
        pvreduce_kernel<<<(TD * Dm + 255) / 256, 256>>>(part, o);
        gemm_pk<<<dim3(TD / 128, Dm / 128, 3), 256, GEMM_SMEM_128>>>(
            o, proj_w + (size_t)l * Dm * Dm, gpart, TD, Dm, Dm, Dm / 3);
        redln_kernel<<<TD, 256>>>(gpart, proj_b + (size_t)l * Dm, x, x,
                                  ln2_g + l * Dm, ln2_b + l * Dm, h, 1e-6f);
        gemm_f32<<<dim3(TD / 128, 4 * Dm / 128), 256, GEMM_SMEM_128>>>(
            h, fc1_w + (size_t)l * Dm * 4 * Dm, fc1_b + (size_t)l * 4 * Dm,
            mlp, TD, 4 * Dm, Dm, 1);
        gemm_pk<<<dim3(TD / 128, Dm / 128, 3), 256, GEMM_SMEM_128>>>(
            mlp, fc2_w + (size_t)l * 4 * Dm * Dm, gpart, TD, Dm, 4 * Dm, 4 * Dm / 3);
        if (l + 1 < Ln) {
            redln_kernel<<<TD, 256>>>(gpart, fc2_b + (size_t)l * Dm, x, x,
                                      ln1_g + (l + 1) * Dm, ln1_b + (l + 1) * Dm, h, 1e-6f);
        } else {
            redln_kernel<<<TD, 256>>>(gpart, fc2_b + (size_t)l * Dm, x, x,
                                      lnf_g, lnf_b, h, 1e-5f);
        }
    }

    cudaStreamWaitEvent(0, evJ, 0);

    gemm_f32<<<dim3(TD / 128, Vv / 128), 256, GEMM_SMEM_128>>>(
        h, wteT, head_b, out, TD, Vv, Dm, 0);
}